// round 6
// baseline (speedup 1.0000x reference)
#include <cuda_runtime.h>
#include <math.h>

#define T_STEPS 512
#define BATCH   128
#define IN_DIM  544
#define HID     512
#define G4H     2048
#define NACT    19
#define NBLK    128
#define NTHR    512     // thread = (batch, unit-slot); 4 warps per SMSP

// ---------------- scratch ----------------------------------------------------
__device__ float g_pre0[(size_t)T_STEPS * G4H * BATCH];     // [t][n][b] transposed
__device__ float g_hidden[(size_t)T_STEPS * BATCH * HID];
__device__ float g_h0[2][BATCH][HID];
__device__ float g_h1[2][BATCH][HID];
__device__ unsigned int g_bar_count;
__device__ unsigned int g_bar_release;

// ---------------- f32x2 helpers ----------------------------------------------
__device__ __forceinline__ void ffma2(unsigned long long& d, unsigned long long a,
                                      unsigned long long b) {
    asm("fma.rn.f32x2 %0, %1, %2, %0;" : "+l"(d) : "l"(a), "l"(b));
}
__device__ __forceinline__ unsigned long long dupf(float a) {
    unsigned long long r; asm("mov.b64 %0, {%1, %1};" : "=l"(r) : "f"(a)); return r;
}
__device__ __forceinline__ float2 unpk(unsigned long long v) {
    float2 r; asm("mov.b64 {%0, %1}, %2;" : "=f"(r.x), "=f"(r.y) : "l"(v)); return r;
}

// ---------------- init -------------------------------------------------------
__global__ void init_kernel(const float* __restrict__ h0) {
    if (blockIdx.x == 0 && threadIdx.x == 0) { g_bar_count = 0u; g_bar_release = 0u; }
    const int n = BATCH * HID;
    for (int i = blockIdx.x * blockDim.x + threadIdx.x; i < n; i += gridDim.x * blockDim.x) {
        (&g_h0[0][0][0])[i] = h0[i];
        (&g_h1[0][0][0])[i] = h0[n + i];
    }
}

// ---------------- precompute GEMM (f32x2) ------------------------------------
// g_pre0[t][n][b] = sum_k X[t*128+b, k] * W_ih0[n, k] + b_ih0[n] + b_hh0[n]
__global__ void __launch_bounds__(256)
pre_gemm_kernel(const float* __restrict__ X, const float* __restrict__ W,
                const float* __restrict__ bA, const float* __restrict__ bB)
{
    __shared__ float Xs[16][68];
    __shared__ float Ws[16][68];
    __shared__ float Ts[64 * 68];
    const int tid = threadIdx.x;
    const int bn  = blockIdx.x * 64;
    const int bm  = blockIdx.y * 64;
    const int tx  = tid & 15;
    const int ty  = tid >> 4;
    const int lm  = tid >> 2;
    const int lk  = (tid & 3) << 2;

    unsigned long long acc2[4][2];
#pragma unroll
    for (int i = 0; i < 4; i++) { acc2[i][0] = 0ull; acc2[i][1] = 0ull; }

    for (int k0 = 0; k0 < IN_DIM; k0 += 16) {
        float4 xa = *(const float4*)&X[(size_t)(bm + lm) * IN_DIM + k0 + lk];
        float4 wa = *(const float4*)&W[(size_t)(bn + lm) * IN_DIM + k0 + lk];
        __syncthreads();
        Xs[lk + 0][lm] = xa.x; Xs[lk + 1][lm] = xa.y; Xs[lk + 2][lm] = xa.z; Xs[lk + 3][lm] = xa.w;
        Ws[lk + 0][lm] = wa.x; Ws[lk + 1][lm] = wa.y; Ws[lk + 2][lm] = wa.z; Ws[lk + 3][lm] = wa.w;
        __syncthreads();
#pragma unroll
        for (int k = 0; k < 16; k++) {
            float4 av = *(const float4*)&Xs[k][ty << 2];
            ulonglong2 bv = *(const ulonglong2*)&Ws[k][tx << 2];
            unsigned long long a0 = dupf(av.x), a1 = dupf(av.y), a2 = dupf(av.z), a3 = dupf(av.w);
            ffma2(acc2[0][0], a0, bv.x); ffma2(acc2[0][1], a0, bv.y);
            ffma2(acc2[1][0], a1, bv.x); ffma2(acc2[1][1], a1, bv.y);
            ffma2(acc2[2][0], a2, bv.x); ffma2(acc2[2][1], a2, bv.y);
            ffma2(acc2[3][0], a3, bv.x); ffma2(acc2[3][1], a3, bv.y);
        }
    }

    float bb[4];
#pragma unroll
    for (int j = 0; j < 4; j++) { int n = bn + (tx << 2) + j; bb[j] = bA[n] + bB[n]; }

    __syncthreads();
#pragma unroll
    for (int i = 0; i < 4; i++) {
        float2 v01 = unpk(acc2[i][0]);
        float2 v23 = unpk(acc2[i][1]);
        int ml = (ty << 2) + i;
        Ts[((tx << 2) + 0) * 68 + ml] = v01.x + bb[0];
        Ts[((tx << 2) + 1) * 68 + ml] = v01.y + bb[1];
        Ts[((tx << 2) + 2) * 68 + ml] = v23.x + bb[2];
        Ts[((tx << 2) + 3) * 68 + ml] = v23.y + bb[3];
    }
    __syncthreads();

    const int tt = bm >> 7;            // time index
    const int b0 = bm & 127;           // batch base (0 or 64)
    const int nl = tid >> 2;
    const int mq = (tid & 3) << 4;
    float* dst = &g_pre0[((size_t)tt * G4H + bn + nl) * BATCH + b0 + mq];
    const float* src = &Ts[nl * 68 + mq];
#pragma unroll
    for (int s = 0; s < 4; s++)
        ((float4*)dst)[s] = ((const float4*)src)[s];
}

// ---------------- persistent LSTM --------------------------------------------
__device__ __forceinline__ float sigmoidf_(float x) { return 1.f / (1.f + expf(-x)); }

__device__ __forceinline__ void grid_bar(unsigned int phase) {
    __threadfence();
    __syncthreads();
    if (threadIdx.x == 0) {
        unsigned int arrived = atomicAdd(&g_bar_count, 1u) + 1u;
        if (arrived == (unsigned)NBLK * phase) {
            atomicExch(&g_bar_release, phase);
        } else {
            while (*(volatile unsigned int*)&g_bar_release < phase) { __nanosleep(64); }
        }
    }
    __syncthreads();
}

// acc2[g] += sum_k h[b,k] * W[gate g of this thread's unit][k]
// Thread owns 1 unit (4 gate rows); W rows broadcast from SMEM (uniform addr).
// Wu points at smem row 'half'; gate g row is at + g*4*HID.
template <bool USE_MASK>
__device__ __forceinline__ void accum_K(unsigned long long* __restrict__ acc2,
                                        const float* __restrict__ hsrc,
                                        const float* __restrict__ Wu,
                                        const float* __restrict__ msm,
                                        float* __restrict__ hbuf,
                                        const int tid, const int b)
{
    const float* hb = &hbuf[b * 132];
    for (int kc = 0; kc < 4; kc++) {
        const int k0 = kc << 7;
        __syncthreads();
#pragma unroll
        for (int it = 0; it < 8; it++) {
            const int idx = (it << 9) + tid;
            const int bl  = idx >> 5;
            const int kq  = (idx & 31) << 2;
            float4 v = __ldcg((const float4*)&hsrc[bl * HID + k0 + kq]);
            if (USE_MASK) { float m = msm[bl]; v.x *= m; v.y *= m; v.z *= m; v.w *= m; }
            *(float4*)&hbuf[bl * 132 + kq] = v;
        }
        __syncthreads();
#pragma unroll 4
        for (int k = 0; k < 128; k += 8) {
            ulonglong2 ha = *(const ulonglong2*)(hb + k);
            ulonglong2 hc = *(const ulonglong2*)(hb + k + 4);
#pragma unroll
            for (int g = 0; g < 4; g++) {
                ulonglong2 w0 = *(const ulonglong2*)(Wu + (g << 11) + k0 + k);
                ulonglong2 w1 = *(const ulonglong2*)(Wu + (g << 11) + k0 + k + 4);
                ffma2(acc2[g], ha.x, w0.x);
                ffma2(acc2[g], ha.y, w0.y);
                ffma2(acc2[g], hc.x, w1.x);
                ffma2(acc2[g], hc.y, w1.y);
            }
        }
    }
}

__global__ void __launch_bounds__(NTHR, 1)
lstm_kernel(const int* __restrict__ done,
            const float* __restrict__ c0_in,
            const float* __restrict__ W_hh0,
            const float* __restrict__ W_ih1,
            const float* __restrict__ W_hh1,
            const float* __restrict__ b_ih1,
            const float* __restrict__ b_hh1,
            float* __restrict__ out_hT,
            float* __restrict__ out_cT)
{
    extern __shared__ float smem[];
    float* W0s  = smem;                    // 16 x 512  (row r = g*4 + unit)
    float* W1i  = W0s + 16 * HID;
    float* W1h  = W1i + 16 * HID;
    float* hbuf = W1h + 16 * HID;          // 128 x 132
    float* msm  = hbuf + 128 * 132;        // 128 masks

    const int tid  = threadIdx.x;
    const int bid  = blockIdx.x;
    const int b    = tid & 127;            // batch element this thread owns
    const int half = tid >> 7;             // unit slot 0..3
    const int u0   = bid * 4;
    const int u    = u0 + half;            // global hidden unit this thread owns

    // load weights: smem row r = g*4+lu  <-  global row g*HID + u0 + lu
    for (int i = tid; i < 16 * (HID / 4); i += NTHR) {
        int r = i >> 7, c4 = i & 127;
        int g = r >> 2, lu = r & 3;
        size_t grow = (size_t)g * HID + u0 + lu;
        ((float4*)W0s)[i] = ((const float4*)W_hh0)[grow * (HID / 4) + c4];
        ((float4*)W1i)[i] = ((const float4*)W_ih1)[grow * (HID / 4) + c4];
        ((float4*)W1h)[i] = ((const float4*)W_hh1)[grow * (HID / 4) + c4];
    }

    float bias1[4];
#pragma unroll
    for (int g = 0; g < 4; g++) bias1[g] = b_ih1[g * HID + u] + b_hh1[g * HID + u];

    float c0r = c0_in[(0 * BATCH + b) * HID + u];
    float c1r = c0_in[(1 * BATCH + b) * HID + u];

    const float* Wu0  = W0s + half * HID;
    const float* Wu1i = W1i + half * HID;
    const float* Wu1h = W1h + half * HID;

    unsigned int phase = 0;

    for (int t = 0; t < T_STEPS; t++) {
        const int p = t & 1;

        if (tid < BATCH) msm[tid] = 1.0f - (float)done[t * BATCH + tid];
        const float mk = 1.0f - (float)done[t * BATCH + b];

        // prefetch pre0 for this thread's 4 gate rows (hidden under accum)
        float pre[4];
        const float* pb = g_pre0 + (size_t)t * G4H * BATCH + b;
#pragma unroll
        for (int g = 0; g < 4; g++)
            pre[g] = __ldcg(&pb[(size_t)(g * HID + u) * BATCH]);

        // ---- layer 0 : gates = pre0 + (h0*mask) @ W_hh0^T ----
        unsigned long long acc2[4];
#pragma unroll
        for (int i = 0; i < 4; i++) acc2[i] = 0ull;
        accum_K<true>(acc2, &g_h0[p][0][0], Wu0, msm, hbuf, tid, b);

        {
            float2 vi = unpk(acc2[0]);
            float2 vf = unpk(acc2[1]);
            float2 vg = unpk(acc2[2]);
            float2 vo = unpk(acc2[3]);
            float ig = sigmoidf_(vi.x + vi.y + pre[0]);
            float fg = sigmoidf_(vf.x + vf.y + pre[1]);
            float gg = tanhf    (vg.x + vg.y + pre[2]);
            float og = sigmoidf_(vo.x + vo.y + pre[3]);
            float c  = fmaf(fg, c0r * mk, ig * gg);
            c0r = c;
            g_h0[p ^ 1][b][u] = og * tanhf(c);
        }

        grid_bar(++phase);

        // ---- layer 1 : gates = b1 + h0_new @ W_ih1^T + (h1*mask) @ W_hh1^T ----
#pragma unroll
        for (int i = 0; i < 4; i++) acc2[i] = 0ull;
        accum_K<false>(acc2, &g_h0[p ^ 1][0][0], Wu1i, msm, hbuf, tid, b);
        accum_K<true >(acc2, &g_h1[p][0][0],     Wu1h, msm, hbuf, tid, b);

        {
            float2 vi = unpk(acc2[0]);
            float2 vf = unpk(acc2[1]);
            float2 vg = unpk(acc2[2]);
            float2 vo = unpk(acc2[3]);
            float ig = sigmoidf_(vi.x + vi.y + bias1[0]);
            float fg = sigmoidf_(vf.x + vf.y + bias1[1]);
            float gg = tanhf    (vg.x + vg.y + bias1[2]);
            float og = sigmoidf_(vo.x + vo.y + bias1[3]);
            float c  = fmaf(fg, c1r * mk, ig * gg);
            c1r = c;
            float h  = og * tanhf(c);
            g_h1[p ^ 1][b][u] = h;
            g_hidden[((size_t)t * BATCH + b) * HID + u] = h;
        }
    }

    grid_bar(++phase);   // all blocks' final-step writes visible before copy-out

    out_cT[(0 * BATCH + b) * HID + u] = c0r;
    out_cT[(1 * BATCH + b) * HID + u] = c1r;

    {
        int i = bid * NTHR + tid;      // NBLK*NTHR == BATCH*HID exactly
        out_hT[i]               = __ldcg(&(&g_h0[0][0][0])[i]);
        out_hT[BATCH * HID + i] = __ldcg(&(&g_h1[0][0][0])[i]);
    }
}

// ---------------- actor/critic heads -----------------------------------------
__global__ void __launch_bounds__(256)
head_kernel(const float* __restrict__ Wa, const float* __restrict__ ba,
            const float* __restrict__ Wc, const float* __restrict__ bc,
            float* __restrict__ out)
{
    __shared__ float Ws[NACT * HID];
    __shared__ float bs[NACT];
    for (int i = threadIdx.x; i < 18 * HID; i += blockDim.x) Ws[i] = Wa[i];
    for (int i = threadIdx.x; i < HID; i += blockDim.x) Ws[18 * HID + i] = Wc[i];
    if (threadIdx.x < 18) bs[threadIdx.x] = ba[threadIdx.x];
    if (threadIdx.x == 18) bs[18] = bc[0];
    __syncthreads();

    const int warp = threadIdx.x >> 5;
    const int lane = threadIdx.x & 31;
    const size_t m = (size_t)blockIdx.x * 8 + warp;

    const float* hrow = &g_hidden[m * HID];
    float hv[16];
#pragma unroll
    for (int j = 0; j < 16; j++) hv[j] = hrow[lane + j * 32];

#pragma unroll
    for (int a = 0; a < NACT; a++) {
        float s = 0.f;
#pragma unroll
        for (int j = 0; j < 16; j++) s = fmaf(hv[j], Ws[a * HID + lane + j * 32], s);
#pragma unroll
        for (int off = 16; off > 0; off >>= 1) s += __shfl_xor_sync(0xffffffffu, s, off);
        if (lane == a) out[m * NACT + a] = s + bs[a];
    }
}

// ---------------- launch ------------------------------------------------------
extern "C" void kernel_launch(void* const* d_in, const int* in_sizes, int n_in,
                              void* d_out, int out_size)
{
    (void)in_sizes; (void)n_in; (void)out_size;
    const float* x     = (const float*)d_in[0];
    const int*   done  = (const int*)  d_in[1];
    const float* h0    = (const float*)d_in[2];
    const float* c0    = (const float*)d_in[3];
    const float* W_ih0 = (const float*)d_in[4];
    const float* W_hh0 = (const float*)d_in[5];
    const float* b_ih0 = (const float*)d_in[6];
    const float* b_hh0 = (const float*)d_in[7];
    const float* W_ih1 = (const float*)d_in[8];
    const float* W_hh1 = (const float*)d_in[9];
    const float* b_ih1 = (const float*)d_in[10];
    const float* b_hh1 = (const float*)d_in[11];
    const float* W_a   = (const float*)d_in[12];
    const float* b_a   = (const float*)d_in[13];
    const float* W_c   = (const float*)d_in[14];
    const float* b_c   = (const float*)d_in[15];

    float* out    = (float*)d_out;
    float* out_hT = out + (size_t)T_STEPS * BATCH * NACT;
    float* out_cT = out_hT + 2 * BATCH * HID;

    const int smem_bytes = (3 * 16 * HID + 128 * 132 + 128) * (int)sizeof(float); // 166,400 B
    cudaFuncSetAttribute(lstm_kernel, cudaFuncAttributeMaxDynamicSharedMemorySize, smem_bytes);

    init_kernel<<<64, 256>>>(h0);

    dim3 gg(G4H / 64, (T_STEPS * BATCH) / 64);
    pre_gemm_kernel<<<gg, 256>>>(x, W_ih0, b_ih0, b_hh0);

    lstm_kernel<<<NBLK, NTHR, smem_bytes>>>(done, c0, W_hh0, W_ih1, W_hh1,
                                            b_ih1, b_hh1, out_hT, out_cT);

    head_kernel<<<(T_STEPS * BATCH) / 8, 256>>>(W_a, b_a, W_c, b_c, out);
}

// round 8
// speedup vs baseline: 2.4371x; 2.4371x over previous
#include <cuda_runtime.h>
#include <math.h>
#include <cstdint>

#define T_STEPS 512
#define BATCH   128
#define IN_DIM  544
#define HID     512
#define G4H     2048
#define NACT    19
#define NCTA    64      // lstm CTAs: each owns 8 hidden units (32 gate rows)
#define TPB     256
#define NU      8       // units per CTA
#define NGR     32      // gate rows per CTA (MMA N)

// SMEM layout (bytes): A tile 128x132 f32, B tile 32x132 f32, masks
#define SM_A     0
#define SM_B     (128 * 528)                  // 67584
#define SM_MSM   (SM_B + 32 * 528)            // 84480
#define SM_TOTAL (SM_MSM + 512 + 128)

// ---------------- scratch ----------------------------------------------------
__device__ float g_pre0[(size_t)T_STEPS * G4H * BATCH];     // [t][n][b]
__device__ float g_hidden[(size_t)T_STEPS * BATCH * HID];
__device__ float g_h0[2][BATCH][HID];                       // tf32-rounded h
__device__ float g_h1[2][BATCH][HID];
__device__ float g_wt0[G4H * HID];                          // tf32-rounded weights
__device__ float g_wt1i[G4H * HID];
__device__ float g_wt1h[G4H * HID];
__device__ unsigned int g_bar_count;
__device__ unsigned int g_bar_release;

// ---------------- helpers ----------------------------------------------------
__device__ __forceinline__ uint32_t smem_u32(const void* p) {
    uint32_t a;
    asm("{ .reg .u64 t; cvta.to.shared.u64 t, %1; cvt.u32.u64 %0, t; }" : "=r"(a) : "l"(p));
    return a;
}
__device__ __forceinline__ float tf32r(float x) {
    uint32_t o; asm("cvt.rna.tf32.f32 %0, %1;" : "=r"(o) : "f"(x));
    return __uint_as_float(o);
}
__device__ __forceinline__ void ldsm4(uint32_t* r, uint32_t addr) {
    asm volatile("ldmatrix.sync.aligned.m8n8.x4.shared.b16 {%0,%1,%2,%3}, [%4];"
                 : "=r"(r[0]), "=r"(r[1]), "=r"(r[2]), "=r"(r[3]) : "r"(addr));
}
__device__ __forceinline__ void mma_tf32(float* d, const uint32_t* a, const uint32_t* b) {
    asm volatile("mma.sync.aligned.m16n8k8.row.col.f32.tf32.tf32.f32 "
                 "{%0,%1,%2,%3}, {%4,%5,%6,%7}, {%8,%9}, {%0,%1,%2,%3};"
                 : "+f"(d[0]), "+f"(d[1]), "+f"(d[2]), "+f"(d[3])
                 : "r"(a[0]), "r"(a[1]), "r"(a[2]), "r"(a[3]), "r"(b[0]), "r"(b[1]));
}
__device__ __forceinline__ float sigmoidf_(float x) { return 1.f / (1.f + expf(-x)); }

// ---------------- init / weight-round kernels --------------------------------
__global__ void init_kernel(const float* __restrict__ h0) {
    if (blockIdx.x == 0 && threadIdx.x == 0) { g_bar_count = 0u; g_bar_release = 0u; }
    const int n = BATCH * HID;
    for (int i = blockIdx.x * blockDim.x + threadIdx.x; i < n; i += gridDim.x * blockDim.x) {
        (&g_h0[0][0][0])[i] = tf32r(h0[i]);
        (&g_h1[0][0][0])[i] = tf32r(h0[n + i]);
    }
}

__global__ void wt_kernel(const float* __restrict__ W0, const float* __restrict__ W1i,
                          const float* __restrict__ W1h) {
    const int n = G4H * HID;
    for (int i = blockIdx.x * blockDim.x + threadIdx.x; i < n; i += gridDim.x * blockDim.x) {
        g_wt0[i]  = tf32r(W0[i]);
        g_wt1i[i] = tf32r(W1i[i]);
        g_wt1h[i] = tf32r(W1h[i]);
    }
}

// ---------------- precompute GEMM (f32x2, unchanged from R4) ------------------
__device__ __forceinline__ void ffma2(unsigned long long& d, unsigned long long a,
                                      unsigned long long b) {
    asm("fma.rn.f32x2 %0, %1, %2, %0;" : "+l"(d) : "l"(a), "l"(b));
}
__device__ __forceinline__ unsigned long long dupf(float a) {
    unsigned long long r; asm("mov.b64 %0, {%1, %1};" : "=l"(r) : "f"(a)); return r;
}
__device__ __forceinline__ float2 unpk(unsigned long long v) {
    float2 r; asm("mov.b64 {%0, %1}, %2;" : "=f"(r.x), "=f"(r.y) : "l"(v)); return r;
}

__global__ void __launch_bounds__(256)
pre_gemm_kernel(const float* __restrict__ X, const float* __restrict__ W,
                const float* __restrict__ bA, const float* __restrict__ bB)
{
    __shared__ float Xs[16][68];
    __shared__ float Ws[16][68];
    __shared__ float Ts[64 * 68];
    const int tid = threadIdx.x;
    const int bn  = blockIdx.x * 64;
    const int bm  = blockIdx.y * 64;
    const int tx  = tid & 15;
    const int ty  = tid >> 4;
    const int lm  = tid >> 2;
    const int lk  = (tid & 3) << 2;

    unsigned long long acc2[4][2];
#pragma unroll
    for (int i = 0; i < 4; i++) { acc2[i][0] = 0ull; acc2[i][1] = 0ull; }

    for (int k0 = 0; k0 < IN_DIM; k0 += 16) {
        float4 xa = *(const float4*)&X[(size_t)(bm + lm) * IN_DIM + k0 + lk];
        float4 wa = *(const float4*)&W[(size_t)(bn + lm) * IN_DIM + k0 + lk];
        __syncthreads();
        Xs[lk + 0][lm] = xa.x; Xs[lk + 1][lm] = xa.y; Xs[lk + 2][lm] = xa.z; Xs[lk + 3][lm] = xa.w;
        Ws[lk + 0][lm] = wa.x; Ws[lk + 1][lm] = wa.y; Ws[lk + 2][lm] = wa.z; Ws[lk + 3][lm] = wa.w;
        __syncthreads();
#pragma unroll
        for (int k = 0; k < 16; k++) {
            float4 av = *(const float4*)&Xs[k][ty << 2];
            ulonglong2 bv = *(const ulonglong2*)&Ws[k][tx << 2];
            unsigned long long a0 = dupf(av.x), a1 = dupf(av.y), a2 = dupf(av.z), a3 = dupf(av.w);
            ffma2(acc2[0][0], a0, bv.x); ffma2(acc2[0][1], a0, bv.y);
            ffma2(acc2[1][0], a1, bv.x); ffma2(acc2[1][1], a1, bv.y);
            ffma2(acc2[2][0], a2, bv.x); ffma2(acc2[2][1], a2, bv.y);
            ffma2(acc2[3][0], a3, bv.x); ffma2(acc2[3][1], a3, bv.y);
        }
    }

    float bb[4];
#pragma unroll
    for (int j = 0; j < 4; j++) { int n = bn + (tx << 2) + j; bb[j] = bA[n] + bB[n]; }

    __syncthreads();
#pragma unroll
    for (int i = 0; i < 4; i++) {
        float2 v01 = unpk(acc2[i][0]);
        float2 v23 = unpk(acc2[i][1]);
        int ml = (ty << 2) + i;
        Ts[((tx << 2) + 0) * 68 + ml] = v01.x + bb[0];
        Ts[((tx << 2) + 1) * 68 + ml] = v01.y + bb[1];
        Ts[((tx << 2) + 2) * 68 + ml] = v23.x + bb[2];
        Ts[((tx << 2) + 3) * 68 + ml] = v23.y + bb[3];
    }
    __syncthreads();

    const int tt = bm >> 7;
    const int b0 = bm & 127;
    const int nl = tid >> 2;
    const int mq = (tid & 3) << 4;
    float* dst = &g_pre0[((size_t)tt * G4H + bn + nl) * BATCH + b0 + mq];
    const float* src = &Ts[nl * 68 + mq];
#pragma unroll
    for (int s = 0; s < 4; s++)
        ((float4*)dst)[s] = ((const float4*)src)[s];
}

// ---------------- persistent tensor (mma.sync) LSTM ---------------------------
__device__ __forceinline__ void grid_bar(unsigned int phase) {
    __threadfence();
    __syncthreads();
    if (threadIdx.x == 0) {
        unsigned int arrived = atomicAdd(&g_bar_count, 1u) + 1u;
        if (arrived == (unsigned)NCTA * phase) {
            atomicExch(&g_bar_release, phase);
        } else {
            while (*(volatile unsigned int*)&g_bar_release < phase) { __nanosleep(64); }
        }
    }
    __syncthreads();
}

// stage A chunk: 128 batch rows x 128 k into [m][132] padded tile
template <bool MASK>
__device__ __forceinline__ void stage_A(char* sm, const float* __restrict__ src,
                                        int kc, const float* __restrict__ msm, int tid)
{
#pragma unroll
    for (int it = 0; it < 16; it++) {
        const int idx = it * TPB + tid;
        const int m  = idx >> 5;
        const int kq = (idx & 31) << 2;
        float4 v = __ldcg((const float4*)&src[m * HID + kc * 128 + kq]);
        if (MASK) { float s = msm[m]; v.x *= s; v.y *= s; v.z *= s; v.w *= s; }
        *(float4*)(sm + SM_A + m * 528 + kq * 4) = v;
    }
}

// stage B chunk: 32 gate rows (gate*8+unit) x 128 k into [n][132] padded tile
__device__ __forceinline__ void stage_B(char* sm, const float* __restrict__ W,
                                        int kc, int u0, int tid)
{
#pragma unroll
    for (int it = 0; it < 4; it++) {
        const int idx = it * TPB + tid;
        const int r  = idx >> 5;                         // 0..31
        const int kq = (idx & 31) << 2;
        const int grow = (r >> 3) * HID + u0 + (r & 7);  // gate*HID + unit
        float4 v = __ldg((const float4*)&W[(size_t)grow * HID + kc * 128 + kq]);
        *(float4*)(sm + SM_B + r * 528 + kq * 4) = v;
    }
}

// compute one 128-K chunk: 16 k-steps of m16n8k8 over 4 n-tiles
__device__ __forceinline__ void chunk_mma(float* acc, uint32_t aA, uint32_t bB0, uint32_t bB1)
{
#pragma unroll
    for (int ks = 0; ks < 16; ks++) {
        uint32_t af[4], b0[4], b1[4];
        ldsm4(af, aA + ks * 32);
        ldsm4(b0, bB0 + ks * 32);
        ldsm4(b1, bB1 + ks * 32);
        mma_tf32(acc + 0,  af, b0 + 0);
        mma_tf32(acc + 4,  af, b0 + 2);
        mma_tf32(acc + 8,  af, b1 + 0);
        mma_tf32(acc + 12, af, b1 + 2);
    }
}

__global__ void __launch_bounds__(TPB, 1)
lstm_kernel(const int* __restrict__ done,
            const float* __restrict__ c0_in,
            const float* __restrict__ b_ih1,
            const float* __restrict__ b_hh1,
            float* __restrict__ out_hT,
            float* __restrict__ out_cT)
{
    extern __shared__ char sm[];
    float* msm = (float*)(sm + SM_MSM);
    float* D_s = (float*)(sm + SM_A);      // D epilogue overlays A tile: [32 n][132]

    const int tid  = threadIdx.x;
    const int w    = tid >> 5;
    const int lane = tid & 31;
    const int u0   = blockIdx.x * NU;

    // ldmatrix lane addresses (fixed for whole kernel)
    const uint32_t sb = smem_u32(sm);
    const int st = lane >> 3;
    const uint32_t aA  = sb + SM_A + (w * 16 + (st & 1) * 8 + (lane & 7)) * 528 + (st >> 1) * 16;
    const uint32_t bB0 = sb + SM_B + ((st >> 1) * 8 + (lane & 7)) * 528 + (st & 1) * 16;
    const uint32_t bB1 = bB0 + 16 * 528;

    // cell-update thread mapping: b = tid&127, unit group = (tid>>7)*4
    const int b  = tid & 127;
    const int ug = (tid >> 7) * 4;

    float bias1[4][4];                     // [j][gate]
#pragma unroll
    for (int j = 0; j < 4; j++)
#pragma unroll
        for (int g = 0; g < 4; g++) {
            int row = g * HID + u0 + ug + j;
            bias1[j][g] = b_ih1[row] + b_hh1[row];
        }

    float c0r[4], c1r[4];
#pragma unroll
    for (int j = 0; j < 4; j++) {
        c0r[j] = c0_in[(0 * BATCH + b) * HID + u0 + ug + j];
        c1r[j] = c0_in[(1 * BATCH + b) * HID + u0 + ug + j];
    }

    unsigned int phase = 0;

    for (int t = 0; t < T_STEPS; t++) {
        const int p = t & 1;

        if (tid < BATCH) msm[tid] = 1.0f - (float)done[t * BATCH + tid];

        // prefetch pre0 for this thread's 16 gate slots (used in epilogue 0)
        float pre[4][4];
#pragma unroll
        for (int j = 0; j < 4; j++)
#pragma unroll
            for (int g = 0; g < 4; g++)
                pre[j][g] = __ldcg(&g_pre0[((size_t)t * G4H + g * HID + u0 + ug + j) * BATCH + b]);

        // ================= layer 0: D = (h0*mask) @ W_hh0^T =================
        float acc[16];
#pragma unroll
        for (int i = 0; i < 16; i++) acc[i] = 0.f;

        for (int kc = 0; kc < 4; kc++) {
            __syncthreads();
            stage_A<true>(sm, &g_h0[p][0][0], kc, msm, tid);
            stage_B(sm, g_wt0, kc, u0, tid);
            __syncthreads();
            chunk_mma(acc, aA, bB0, bB1);
        }

        // epilogue 0: D -> smem -> cell update
        __syncthreads();
        {
            const int r = lane >> 2, c2 = (lane & 3) * 2;
#pragma unroll
            for (int nt = 0; nt < 4; nt++) {
                const int n = nt * 8 + c2;
                D_s[(n + 0) * 132 + w * 16 + r]     = acc[nt * 4 + 0];
                D_s[(n + 1) * 132 + w * 16 + r]     = acc[nt * 4 + 1];
                D_s[(n + 0) * 132 + w * 16 + r + 8] = acc[nt * 4 + 2];
                D_s[(n + 1) * 132 + w * 16 + r + 8] = acc[nt * 4 + 3];
            }
        }
        __syncthreads();
        {
            const float mk = msm[b];
#pragma unroll
            for (int j = 0; j < 4; j++) {
                const int u = ug + j;
                float gi = D_s[(0 * 8 + u) * 132 + b] + pre[j][0];
                float gf = D_s[(1 * 8 + u) * 132 + b] + pre[j][1];
                float gg = D_s[(2 * 8 + u) * 132 + b] + pre[j][2];
                float go = D_s[(3 * 8 + u) * 132 + b] + pre[j][3];
                float c  = fmaf(sigmoidf_(gf), c0r[j] * mk, sigmoidf_(gi) * tanhf(gg));
                c0r[j]   = c;
                g_h0[p ^ 1][b][u0 + u] = tf32r(sigmoidf_(go) * tanhf(c));
            }
        }

        grid_bar(++phase);

        // ========== layer 1: D = h0_new @ W_ih1^T + (h1*mask) @ W_hh1^T ==========
#pragma unroll
        for (int i = 0; i < 16; i++) acc[i] = 0.f;

        for (int kc = 0; kc < 8; kc++) {
            __syncthreads();
            if (kc < 4) stage_A<false>(sm, &g_h0[p ^ 1][0][0], kc, msm, tid);
            else        stage_A<true >(sm, &g_h1[p][0][0], kc - 4, msm, tid);
            stage_B(sm, (kc < 4) ? g_wt1i : g_wt1h, kc & 3, u0, tid);
            __syncthreads();
            chunk_mma(acc, aA, bB0, bB1);
        }

        __syncthreads();
        {
            const int r = lane >> 2, c2 = (lane & 3) * 2;
#pragma unroll
            for (int nt = 0; nt < 4; nt++) {
                const int n = nt * 8 + c2;
                D_s[(n + 0) * 132 + w * 16 + r]     = acc[nt * 4 + 0];
                D_s[(n + 1) * 132 + w * 16 + r]     = acc[nt * 4 + 1];
                D_s[(n + 0) * 132 + w * 16 + r + 8] = acc[nt * 4 + 2];
                D_s[(n + 1) * 132 + w * 16 + r + 8] = acc[nt * 4 + 3];
            }
        }
        __syncthreads();
        {
            const float mk = msm[b];
#pragma unroll
            for (int j = 0; j < 4; j++) {
                const int u = ug + j;
                float gi = D_s[(0 * 8 + u) * 132 + b] + bias1[j][0];
                float gf = D_s[(1 * 8 + u) * 132 + b] + bias1[j][1];
                float gg = D_s[(2 * 8 + u) * 132 + b] + bias1[j][2];
                float go = D_s[(3 * 8 + u) * 132 + b] + bias1[j][3];
                float c  = fmaf(sigmoidf_(gf), c1r[j] * mk, sigmoidf_(gi) * tanhf(gg));
                c1r[j]   = c;
                float h  = tf32r(sigmoidf_(go) * tanhf(c));
                g_h1[p ^ 1][b][u0 + u] = h;
                g_hidden[((size_t)t * BATCH + b) * HID + u0 + u] = h;
            }
        }
        // one barrier per step: next step's grid_bar orders h1 for other CTAs
    }

    grid_bar(++phase);   // final writes visible before copy-out

#pragma unroll
    for (int j = 0; j < 4; j++) {
        out_cT[(0 * BATCH + b) * HID + u0 + ug + j] = c0r[j];
        out_cT[(1 * BATCH + b) * HID + u0 + ug + j] = c1r[j];
    }
    for (int i = blockIdx.x * TPB + tid; i < BATCH * HID; i += NCTA * TPB) {
        out_hT[i]               = __ldcg(&(&g_h0[0][0][0])[i]);
        out_hT[BATCH * HID + i] = __ldcg(&(&g_h1[0][0][0])[i]);
    }
}

// ---------------- actor/critic heads -----------------------------------------
__global__ void __launch_bounds__(256)
head_kernel(const float* __restrict__ Wa, const float* __restrict__ ba,
            const float* __restrict__ Wc, const float* __restrict__ bc,
            float* __restrict__ out)
{
    __shared__ float Ws[NACT * HID];
    __shared__ float bs[NACT];
    for (int i = threadIdx.x; i < 18 * HID; i += blockDim.x) Ws[i] = Wa[i];
    for (int i = threadIdx.x; i < HID; i += blockDim.x) Ws[18 * HID + i] = Wc[i];
    if (threadIdx.x < 18) bs[threadIdx.x] = ba[threadIdx.x];
    if (threadIdx.x == 18) bs[18] = bc[0];
    __syncthreads();

    const int warp = threadIdx.x >> 5;
    const int lane = threadIdx.x & 31;
    const size_t m = (size_t)blockIdx.x * 8 + warp;

    const float* hrow = &g_hidden[m * HID];
    float hv[16];
#pragma unroll
    for (int j = 0; j < 16; j++) hv[j] = hrow[lane + j * 32];

#pragma unroll
    for (int a = 0; a < NACT; a++) {
        float s = 0.f;
#pragma unroll
        for (int j = 0; j < 16; j++) s = fmaf(hv[j], Ws[a * HID + lane + j * 32], s);
#pragma unroll
        for (int off = 16; off > 0; off >>= 1) s += __shfl_xor_sync(0xffffffffu, s, off);
        if (lane == a) out[m * NACT + a] = s + bs[a];
    }
}

// ---------------- launch ------------------------------------------------------
extern "C" void kernel_launch(void* const* d_in, const int* in_sizes, int n_in,
                              void* d_out, int out_size)
{
    (void)in_sizes; (void)n_in; (void)out_size;
    const float* x     = (const float*)d_in[0];
    const int*   done  = (const int*)  d_in[1];
    const float* h0    = (const float*)d_in[2];
    const float* c0    = (const float*)d_in[3];
    const float* W_ih0 = (const float*)d_in[4];
    const float* W_hh0 = (const float*)d_in[5];
    const float* b_ih0 = (const float*)d_in[6];
    const float* b_hh0 = (const float*)d_in[7];
    const float* W_ih1 = (const float*)d_in[8];
    const float* W_hh1 = (const float*)d_in[9];
    const float* b_ih1 = (const float*)d_in[10];
    const float* b_hh1 = (const float*)d_in[11];
    const float* W_a   = (const float*)d_in[12];
    const float* b_a   = (const float*)d_in[13];
    const float* W_c   = (const float*)d_in[14];
    const float* b_c   = (const float*)d_in[15];

    float* out    = (float*)d_out;
    float* out_hT = out + (size_t)T_STEPS * BATCH * NACT;
    float* out_cT = out_hT + 2 * BATCH * HID;

    cudaFuncSetAttribute(lstm_kernel, cudaFuncAttributeMaxDynamicSharedMemorySize, SM_TOTAL);

    init_kernel<<<64, 256>>>(h0);
    wt_kernel<<<132, 256>>>(W_hh0, W_ih1, W_hh1);

    dim3 gg(G4H / 64, (T_STEPS * BATCH) / 64);
    pre_gemm_kernel<<<gg, 256>>>(x, W_ih0, b_ih0, b_hh0);

    lstm_kernel<<<NCTA, TPB, SM_TOTAL>>>(done, c0, b_ih1, b_hh1, out_hT, out_cT);

    head_kernel<<<(T_STEPS * BATCH) / 8, 256>>>(W_a, b_a, W_c, b_c, out);
}

// round 9
// speedup vs baseline: 2.4901x; 1.0217x over previous
#include <cuda_runtime.h>
#include <math.h>
#include <cstdint>

#define T_STEPS 512
#define BATCH   128
#define IN_DIM  544
#define HID     512
#define G4H     2048
#define NACT    19
#define NCTA    64      // lstm CTAs: each owns 8 hidden units (32 gate rows)
#define TPB     512     // 16 warps: warp = (m-tile, n-pair)
#define NU      8       // units per CTA

// SMEM layout (bytes): A tile 128x132 f32, B tile 32x132 f32, masks
#define SM_A     0
#define SM_B     (128 * 528)                  // 67584
#define SM_MSM   (SM_B + 32 * 528)            // 84480
#define SM_TOTAL (SM_MSM + 512 + 128)

// ---------------- scratch ----------------------------------------------------
__device__ float g_pre0[(size_t)T_STEPS * G4H * BATCH];     // [t][n][b]
__device__ float g_hidden[(size_t)T_STEPS * BATCH * HID];
__device__ float g_h0[2][BATCH][HID];                       // tf32-rounded h
__device__ float g_h1[2][BATCH][HID];
__device__ float g_wt0[G4H * HID];                          // tf32-rounded weights
__device__ float g_wt1i[G4H * HID];
__device__ float g_wt1h[G4H * HID];
__device__ unsigned int g_bar_count;
__device__ unsigned int g_bar_release;

// ---------------- helpers ----------------------------------------------------
__device__ __forceinline__ uint32_t smem_u32(const void* p) {
    uint32_t a;
    asm("{ .reg .u64 t; cvta.to.shared.u64 t, %1; cvt.u32.u64 %0, t; }" : "=r"(a) : "l"(p));
    return a;
}
__device__ __forceinline__ float tf32r(float x) {
    uint32_t o; asm("cvt.rna.tf32.f32 %0, %1;" : "=r"(o) : "f"(x));
    return __uint_as_float(o);
}
__device__ __forceinline__ void ldsm4(uint32_t* r, uint32_t addr) {
    asm volatile("ldmatrix.sync.aligned.m8n8.x4.shared.b16 {%0,%1,%2,%3}, [%4];"
                 : "=r"(r[0]), "=r"(r[1]), "=r"(r[2]), "=r"(r[3]) : "r"(addr));
}
__device__ __forceinline__ void mma_tf32(float* d, const uint32_t* a, const uint32_t* b) {
    asm volatile("mma.sync.aligned.m16n8k8.row.col.f32.tf32.tf32.f32 "
                 "{%0,%1,%2,%3}, {%4,%5,%6,%7}, {%8,%9}, {%0,%1,%2,%3};"
                 : "+f"(d[0]), "+f"(d[1]), "+f"(d[2]), "+f"(d[3])
                 : "r"(a[0]), "r"(a[1]), "r"(a[2]), "r"(a[3]), "r"(b[0]), "r"(b[1]));
}
__device__ __forceinline__ float sigmoidf_(float x) { return 1.f / (1.f + expf(-x)); }

// ---------------- init / weight-round kernels --------------------------------
__global__ void init_kernel(const float* __restrict__ h0) {
    if (blockIdx.x == 0 && threadIdx.x == 0) { g_bar_count = 0u; g_bar_release = 0u; }
    const int n = BATCH * HID;
    for (int i = blockIdx.x * blockDim.x + threadIdx.x; i < n; i += gridDim.x * blockDim.x) {
        (&g_h0[0][0][0])[i] = tf32r(h0[i]);
        (&g_h1[0][0][0])[i] = tf32r(h0[n + i]);
    }
}

__global__ void wt_kernel(const float* __restrict__ W0, const float* __restrict__ W1i,
                          const float* __restrict__ W1h) {
    const int n = G4H * HID;
    for (int i = blockIdx.x * blockDim.x + threadIdx.x; i < n; i += gridDim.x * blockDim.x) {
        g_wt0[i]  = tf32r(W0[i]);
        g_wt1i[i] = tf32r(W1i[i]);
        g_wt1h[i] = tf32r(W1h[i]);
    }
}

// ---------------- precompute GEMM (f32x2, unchanged) --------------------------
__device__ __forceinline__ void ffma2(unsigned long long& d, unsigned long long a,
                                      unsigned long long b) {
    asm("fma.rn.f32x2 %0, %1, %2, %0;" : "+l"(d) : "l"(a), "l"(b));
}
__device__ __forceinline__ unsigned long long dupf(float a) {
    unsigned long long r; asm("mov.b64 %0, {%1, %1};" : "=l"(r) : "f"(a)); return r;
}
__device__ __forceinline__ float2 unpk(unsigned long long v) {
    float2 r; asm("mov.b64 {%0, %1}, %2;" : "=f"(r.x), "=f"(r.y) : "l"(v)); return r;
}

__global__ void __launch_bounds__(256)
pre_gemm_kernel(const float* __restrict__ X, const float* __restrict__ W,
                const float* __restrict__ bA, const float* __restrict__ bB)
{
    __shared__ float Xs[16][68];
    __shared__ float Ws[16][68];
    __shared__ float Ts[64 * 68];
    const int tid = threadIdx.x;
    const int bn  = blockIdx.x * 64;
    const int bm  = blockIdx.y * 64;
    const int tx  = tid & 15;
    const int ty  = tid >> 4;
    const int lm  = tid >> 2;
    const int lk  = (tid & 3) << 2;

    unsigned long long acc2[4][2];
#pragma unroll
    for (int i = 0; i < 4; i++) { acc2[i][0] = 0ull; acc2[i][1] = 0ull; }

    for (int k0 = 0; k0 < IN_DIM; k0 += 16) {
        float4 xa = *(const float4*)&X[(size_t)(bm + lm) * IN_DIM + k0 + lk];
        float4 wa = *(const float4*)&W[(size_t)(bn + lm) * IN_DIM + k0 + lk];
        __syncthreads();
        Xs[lk + 0][lm] = xa.x; Xs[lk + 1][lm] = xa.y; Xs[lk + 2][lm] = xa.z; Xs[lk + 3][lm] = xa.w;
        Ws[lk + 0][lm] = wa.x; Ws[lk + 1][lm] = wa.y; Ws[lk + 2][lm] = wa.z; Ws[lk + 3][lm] = wa.w;
        __syncthreads();
#pragma unroll
        for (int k = 0; k < 16; k++) {
            float4 av = *(const float4*)&Xs[k][ty << 2];
            ulonglong2 bv = *(const ulonglong2*)&Ws[k][tx << 2];
            unsigned long long a0 = dupf(av.x), a1 = dupf(av.y), a2 = dupf(av.z), a3 = dupf(av.w);
            ffma2(acc2[0][0], a0, bv.x); ffma2(acc2[0][1], a0, bv.y);
            ffma2(acc2[1][0], a1, bv.x); ffma2(acc2[1][1], a1, bv.y);
            ffma2(acc2[2][0], a2, bv.x); ffma2(acc2[2][1], a2, bv.y);
            ffma2(acc2[3][0], a3, bv.x); ffma2(acc2[3][1], a3, bv.y);
        }
    }

    float bb[4];
#pragma unroll
    for (int j = 0; j < 4; j++) { int n = bn + (tx << 2) + j; bb[j] = bA[n] + bB[n]; }

    __syncthreads();
#pragma unroll
    for (int i = 0; i < 4; i++) {
        float2 v01 = unpk(acc2[i][0]);
        float2 v23 = unpk(acc2[i][1]);
        int ml = (ty << 2) + i;
        Ts[((tx << 2) + 0) * 68 + ml] = v01.x + bb[0];
        Ts[((tx << 2) + 1) * 68 + ml] = v01.y + bb[1];
        Ts[((tx << 2) + 2) * 68 + ml] = v23.x + bb[2];
        Ts[((tx << 2) + 3) * 68 + ml] = v23.y + bb[3];
    }
    __syncthreads();

    const int tt = bm >> 7;
    const int b0 = bm & 127;
    const int nl = tid >> 2;
    const int mq = (tid & 3) << 4;
    float* dst = &g_pre0[((size_t)tt * G4H + bn + nl) * BATCH + b0 + mq];
    const float* src = &Ts[nl * 68 + mq];
#pragma unroll
    for (int s = 0; s < 4; s++)
        ((float4*)dst)[s] = ((const float4*)src)[s];
}

// ---------------- persistent tensor (mma.sync) LSTM ---------------------------
__device__ __forceinline__ void grid_bar(unsigned int phase) {
    __threadfence();
    __syncthreads();
    if (threadIdx.x == 0) {
        unsigned int arrived = atomicAdd(&g_bar_count, 1u) + 1u;
        if (arrived == (unsigned)NCTA * phase) {
            atomicExch(&g_bar_release, phase);
        } else {
            while (*(volatile unsigned int*)&g_bar_release < phase) { __nanosleep(64); }
        }
    }
    __syncthreads();
}

// prefetch registers for one chunk (per thread): A 8 x float4, B 2 x float4
struct Pf { float4 a[8]; float4 b[2]; };

__device__ __forceinline__ void ld_pf(Pf& pf, const float* __restrict__ srcA,
                                      const float* __restrict__ srcB, int kc, int u0, int tid)
{
#pragma unroll
    for (int it = 0; it < 8; it++) {
        const int idx = it * TPB + tid;
        const int m  = idx >> 5;
        const int kq = (idx & 31) << 2;
        pf.a[it] = __ldcg((const float4*)&srcA[m * HID + kc * 128 + kq]);
    }
#pragma unroll
    for (int it = 0; it < 2; it++) {
        const int idx = it * TPB + tid;
        const int r  = idx >> 5;                         // 0..31
        const int kq = (idx & 31) << 2;
        const int grow = (r >> 3) * HID + u0 + (r & 7);  // gate*HID + unit
        pf.b[it] = __ldg((const float4*)&srcB[(size_t)grow * HID + kc * 128 + kq]);
    }
}

__device__ __forceinline__ void sts_pf(char* sm, const Pf& pf, bool domask,
                                       const float* __restrict__ msm, int tid)
{
#pragma unroll
    for (int it = 0; it < 8; it++) {
        const int idx = it * TPB + tid;
        const int m  = idx >> 5;
        const int kq = (idx & 31) << 2;
        float4 v = pf.a[it];
        if (domask) { float s = msm[m]; v.x *= s; v.y *= s; v.z *= s; v.w *= s; }
        *(float4*)(sm + SM_A + m * 528 + kq * 4) = v;
    }
#pragma unroll
    for (int it = 0; it < 2; it++) {
        const int idx = it * TPB + tid;
        const int r  = idx >> 5;
        const int kq = (idx & 31) << 2;
        *(float4*)(sm + SM_B + r * 528 + kq * 4) = pf.b[it];
    }
}

// one 128-K chunk: warp covers m-tile mt x 2 n-tiles (n-pair np)
__device__ __forceinline__ void chunk_mma(float* acc, uint32_t aA, uint32_t bB)
{
#pragma unroll
    for (int ks = 0; ks < 16; ks++) {
        uint32_t af[4], bf[4];
        ldsm4(af, aA + ks * 32);
        ldsm4(bf, bB + ks * 32);
        mma_tf32(acc + 0, af, bf + 0);
        mma_tf32(acc + 4, af, bf + 2);
    }
}

__global__ void __launch_bounds__(TPB, 1)
lstm_kernel(const int* __restrict__ done,
            const float* __restrict__ c0_in,
            const float* __restrict__ b_ih1,
            const float* __restrict__ b_hh1,
            float* __restrict__ out_hT,
            float* __restrict__ out_cT)
{
    extern __shared__ char sm[];
    float* msm = (float*)(sm + SM_MSM);
    float* D_s = (float*)(sm + SM_A);      // D epilogue overlays A tile: [32 n][132]

    const int tid  = threadIdx.x;
    const int w    = tid >> 5;
    const int lane = tid & 31;
    const int u0   = blockIdx.x * NU;
    const int mt   = w >> 1;               // m-tile 0..7
    const int np   = w & 1;                // n-pair 0..1 (16 gate rows)

    // ldmatrix lane addresses (fixed for whole kernel)
    const uint32_t sb = smem_u32(sm);
    const int st = lane >> 3;
    const uint32_t aA = sb + SM_A + (mt * 16 + (st & 1) * 8 + (lane & 7)) * 528 + (st >> 1) * 16;
    const uint32_t bB = sb + SM_B + (np * 16 + (st >> 1) * 8 + (lane & 7)) * 528 + (st & 1) * 16;

    // cell-update thread mapping: b = tid&127, unit group = (tid>>7)*2
    const int b  = tid & 127;
    const int ug = (tid >> 7) * 2;

    float bias1[2][4];                     // [j][gate]
#pragma unroll
    for (int j = 0; j < 2; j++)
#pragma unroll
        for (int g = 0; g < 4; g++) {
            int row = g * HID + u0 + ug + j;
            bias1[j][g] = b_ih1[row] + b_hh1[row];
        }

    float c0r[2], c1r[2];
#pragma unroll
    for (int j = 0; j < 2; j++) {
        c0r[j] = c0_in[(0 * BATCH + b) * HID + u0 + ug + j];
        c1r[j] = c0_in[(1 * BATCH + b) * HID + u0 + ug + j];
    }

    unsigned int phase = 0;
    Pf pf;

    for (int t = 0; t < T_STEPS; t++) {
        const int p = t & 1;

        if (tid < BATCH) msm[tid] = 1.0f - (float)done[t * BATCH + tid];
        const float mk = 1.0f - (float)__ldg(&done[t * BATCH + b]);   // race-free mask

        // prefetch pre0 for this thread's 8 gate slots (used in epilogue 0)
        float pre[2][4];
#pragma unroll
        for (int j = 0; j < 2; j++)
#pragma unroll
            for (int g = 0; g < 4; g++)
                pre[j][g] = __ldcg(&g_pre0[((size_t)t * G4H + g * HID + u0 + ug + j) * BATCH + b]);

        // ================= layer 0: D = (h0*mask) @ W_hh0^T =================
        float acc[8];
#pragma unroll
        for (int i = 0; i < 8; i++) acc[i] = 0.f;

        ld_pf(pf, &g_h0[p][0][0], g_wt0, 0, u0, tid);          // prime chunk 0
        for (int kc = 0; kc < 4; kc++) {
            __syncthreads();                                    // tile free
            sts_pf(sm, pf, true, msm, tid);
            if (kc + 1 < 4) ld_pf(pf, &g_h0[p][0][0], g_wt0, kc + 1, u0, tid);
            __syncthreads();                                    // tile ready
            chunk_mma(acc, aA, bB);                             // overlaps next LDG
        }

        // epilogue 0: D -> smem -> cell update
        __syncthreads();
        {
            const int r = lane >> 2, c2 = (lane & 3) * 2;
#pragma unroll
            for (int nt = 0; nt < 2; nt++) {
                const int n = np * 16 + nt * 8 + c2;
                D_s[(n + 0) * 132 + mt * 16 + r]     = acc[nt * 4 + 0];
                D_s[(n + 1) * 132 + mt * 16 + r]     = acc[nt * 4 + 1];
                D_s[(n + 0) * 132 + mt * 16 + r + 8] = acc[nt * 4 + 2];
                D_s[(n + 1) * 132 + mt * 16 + r + 8] = acc[nt * 4 + 3];
            }
        }
        __syncthreads();
        {
#pragma unroll
            for (int j = 0; j < 2; j++) {
                const int u = ug + j;
                float gi = D_s[(0 * 8 + u) * 132 + b] + pre[j][0];
                float gf = D_s[(1 * 8 + u) * 132 + b] + pre[j][1];
                float gg = D_s[(2 * 8 + u) * 132 + b] + pre[j][2];
                float go = D_s[(3 * 8 + u) * 132 + b] + pre[j][3];
                float c  = fmaf(sigmoidf_(gf), c0r[j] * mk, sigmoidf_(gi) * tanhf(gg));
                c0r[j]   = c;
                g_h0[p ^ 1][b][u0 + u] = tf32r(sigmoidf_(go) * tanhf(c));
            }
        }

        grid_bar(++phase);

        // ========== layer 1: D = h0_new @ W_ih1^T + (h1*mask) @ W_hh1^T ==========
#pragma unroll
        for (int i = 0; i < 8; i++) acc[i] = 0.f;

        ld_pf(pf, &g_h0[p ^ 1][0][0], g_wt1i, 0, u0, tid);     // prime (after bar)
        for (int kc = 0; kc < 8; kc++) {
            __syncthreads();
            sts_pf(sm, pf, kc >= 4, msm, tid);
            if (kc + 1 < 8) {
                if (kc + 1 < 4) ld_pf(pf, &g_h0[p ^ 1][0][0], g_wt1i, kc + 1, u0, tid);
                else            ld_pf(pf, &g_h1[p][0][0],     g_wt1h, (kc + 1) & 3, u0, tid);
            }
            __syncthreads();
            chunk_mma(acc, aA, bB);
        }

        __syncthreads();
        {
            const int r = lane >> 2, c2 = (lane & 3) * 2;
#pragma unroll
            for (int nt = 0; nt < 2; nt++) {
                const int n = np * 16 + nt * 8 + c2;
                D_s[(n + 0) * 132 + mt * 16 + r]     = acc[nt * 4 + 0];
                D_s[(n + 1) * 132 + mt * 16 + r]     = acc[nt * 4 + 1];
                D_s[(n + 0) * 132 + mt * 16 + r + 8] = acc[nt * 4 + 2];
                D_s[(n + 1) * 132 + mt * 16 + r + 8] = acc[nt * 4 + 3];
            }
        }
        __syncthreads();
        {
#pragma unroll
            for (int j = 0; j < 2; j++) {
                const int u = ug + j;
                float gi = D_s[(0 * 8 + u) * 132 + b] + bias1[j][0];
                float gf = D_s[(1 * 8 + u) * 132 + b] + bias1[j][1];
                float gg = D_s[(2 * 8 + u) * 132 + b] + bias1[j][2];
                float go = D_s[(3 * 8 + u) * 132 + b] + bias1[j][3];
                float c  = fmaf(sigmoidf_(gf), c1r[j] * mk, sigmoidf_(gi) * tanhf(gg));
                c1r[j]   = c;
                float h  = tf32r(sigmoidf_(go) * tanhf(c));
                g_h1[p ^ 1][b][u0 + u] = h;
                g_hidden[((size_t)t * BATCH + b) * HID + u0 + u] = h;
            }
        }
        // one barrier per step: next step's grid_bar orders h1 for other CTAs
    }

    grid_bar(++phase);   // final writes visible before copy-out

#pragma unroll
    for (int j = 0; j < 2; j++) {
        out_cT[(0 * BATCH + b) * HID + u0 + ug + j] = c0r[j];
        out_cT[(1 * BATCH + b) * HID + u0 + ug + j] = c1r[j];
    }
    for (int i = blockIdx.x * TPB + tid; i < BATCH * HID; i += NCTA * TPB) {
        out_hT[i]               = __ldcg(&(&g_h0[0][0][0])[i]);
        out_hT[BATCH * HID + i] = __ldcg(&(&g_h1[0][0][0])[i]);
    }
}

// ---------------- actor/critic heads -----------------------------------------
__global__ void __launch_bounds__(256)
head_kernel(const float* __restrict__ Wa, const float* __restrict__ ba,
            const float* __restrict__ Wc, const float* __restrict__ bc,
            float* __restrict__ out)
{
    __shared__ float Ws[NACT * HID];
    __shared__ float bs[NACT];
    for (int i = threadIdx.x; i < 18 * HID; i += blockDim.x) Ws[i] = Wa[i];
    for (int i = threadIdx.x; i < HID; i += blockDim.x) Ws[18 * HID + i] = Wc[i];
    if (threadIdx.x < 18) bs[threadIdx.x] = ba[threadIdx.x];
    if (threadIdx.x == 18) bs[18] = bc[0];
    __syncthreads();

    const int warp = threadIdx.x >> 5;
    const int lane = threadIdx.x & 31;
    const size_t m = (size_t)blockIdx.x * 8 + warp;

    const float* hrow = &g_hidden[m * HID];
    float hv[16];
#pragma unroll
    for (int j = 0; j < 16; j++) hv[j] = hrow[lane + j * 32];

#pragma unroll
    for (int a = 0; a < NACT; a++) {
        float s = 0.f;
#pragma unroll
        for (int j = 0; j < 16; j++) s = fmaf(hv[j], Ws[a * HID + lane + j * 32], s);
#pragma unroll
        for (int off = 16; off > 0; off >>= 1) s += __shfl_xor_sync(0xffffffffu, s, off);
        if (lane == a) out[m * NACT + a] = s + bs[a];
    }
}

// ---------------- launch ------------------------------------------------------
extern "C" void kernel_launch(void* const* d_in, const int* in_sizes, int n_in,
                              void* d_out, int out_size)
{
    (void)in_sizes; (void)n_in; (void)out_size;
    const float* x     = (const float*)d_in[0];
    const int*   done  = (const int*)  d_in[1];
    const float* h0    = (const float*)d_in[2];
    const float* c0    = (const float*)d_in[3];
    const float* W_ih0 = (const float*)d_in[4];
    const float* W_hh0 = (const float*)d_in[5];
    const float* b_ih0 = (const float*)d_in[6];
    const float* b_hh0 = (const float*)d_in[7];
    const float* W_ih1 = (const float*)d_in[8];
    const float* W_hh1 = (const float*)d_in[9];
    const float* b_ih1 = (const float*)d_in[10];
    const float* b_hh1 = (const float*)d_in[11];
    const float* W_a   = (const float*)d_in[12];
    const float* b_a   = (const float*)d_in[13];
    const float* W_c   = (const float*)d_in[14];
    const float* b_c   = (const float*)d_in[15];

    float* out    = (float*)d_out;
    float* out_hT = out + (size_t)T_STEPS * BATCH * NACT;
    float* out_cT = out_hT + 2 * BATCH * HID;

    cudaFuncSetAttribute(lstm_kernel, cudaFuncAttributeMaxDynamicSharedMemorySize, SM_TOTAL);

    init_kernel<<<64, 256>>>(h0);
    wt_kernel<<<132, 256>>>(W_hh0, W_ih1, W_hh1);

    dim3 gg(G4H / 64, (T_STEPS * BATCH) / 64);
    pre_gemm_kernel<<<gg, 256>>>(x, W_ih0, b_ih0, b_hh0);

    lstm_kernel<<<NCTA, TPB, SM_TOTAL>>>(done, c0, b_ih1, b_hh1, out_hT, out_cT);

    head_kernel<<<(T_STEPS * BATCH) / 8, 256>>>(W_a, b_a, W_c, b_c, out);
}

// round 10
// speedup vs baseline: 3.5128x; 1.4107x over previous
#include <cuda_runtime.h>
#include <math.h>
#include <cstdint>

#define T_STEPS 512
#define BATCH   128
#define IN_DIM  544
#define HID     512
#define G4H     2048
#define NACT    19
#define NCTA    128     // CTA = (batch-half, unit-group of 8)
#define TPB     256     // 8 warps: warp = (m-tile 0..3, n-pair 0..1)
#define NU      8       // units per CTA (32 gate rows)

// SMEM layout (bytes): A tile 64x132 f32, B tile 32x132 f32, masks
#define SM_A     0
#define SM_B     (64 * 528)                   // 33792
#define SM_MSM   (SM_B + 32 * 528)            // 50688
#define SM_TOTAL (SM_MSM + 512)

// ---------------- scratch ----------------------------------------------------
__device__ float g_pre0[(size_t)T_STEPS * G4H * BATCH];     // [t][n][b]
__device__ float g_hidden[(size_t)T_STEPS * BATCH * HID];
__device__ float g_h0[2][BATCH][HID];                       // tf32-rounded h
__device__ float g_h1[2][BATCH][HID];
__device__ float g_wt0[G4H * HID];                          // tf32-rounded weights
__device__ float g_wt1i[G4H * HID];
__device__ float g_wt1h[G4H * HID];
__device__ unsigned int g_bar_count;
__device__ unsigned int g_bar_release;

// ---------------- helpers ----------------------------------------------------
__device__ __forceinline__ uint32_t smem_u32(const void* p) {
    uint32_t a;
    asm("{ .reg .u64 t; cvta.to.shared.u64 t, %1; cvt.u32.u64 %0, t; }" : "=r"(a) : "l"(p));
    return a;
}
__device__ __forceinline__ float tf32r(float x) {
    uint32_t o; asm("cvt.rna.tf32.f32 %0, %1;" : "=r"(o) : "f"(x));
    return __uint_as_float(o);
}
__device__ __forceinline__ void ldsm4(uint32_t* r, uint32_t addr) {
    asm volatile("ldmatrix.sync.aligned.m8n8.x4.shared.b16 {%0,%1,%2,%3}, [%4];"
                 : "=r"(r[0]), "=r"(r[1]), "=r"(r[2]), "=r"(r[3]) : "r"(addr));
}
__device__ __forceinline__ void mma_tf32(float* d, const uint32_t* a, const uint32_t* b) {
    asm volatile("mma.sync.aligned.m16n8k8.row.col.f32.tf32.tf32.f32 "
                 "{%0,%1,%2,%3}, {%4,%5,%6,%7}, {%8,%9}, {%0,%1,%2,%3};"
                 : "+f"(d[0]), "+f"(d[1]), "+f"(d[2]), "+f"(d[3])
                 : "r"(a[0]), "r"(a[1]), "r"(a[2]), "r"(a[3]), "r"(b[0]), "r"(b[1]));
}
__device__ __forceinline__ float sigmoidf_(float x) { return 1.f / (1.f + expf(-x)); }

// ---------------- init / weight-round kernels --------------------------------
__global__ void init_kernel(const float* __restrict__ h0) {
    if (blockIdx.x == 0 && threadIdx.x == 0) { g_bar_count = 0u; g_bar_release = 0u; }
    const int n = BATCH * HID;
    for (int i = blockIdx.x * blockDim.x + threadIdx.x; i < n; i += gridDim.x * blockDim.x) {
        (&g_h0[0][0][0])[i] = tf32r(h0[i]);
        (&g_h1[0][0][0])[i] = tf32r(h0[n + i]);
    }
}

__global__ void wt_kernel(const float* __restrict__ W0, const float* __restrict__ W1i,
                          const float* __restrict__ W1h) {
    const int n = G4H * HID;
    for (int i = blockIdx.x * blockDim.x + threadIdx.x; i < n; i += gridDim.x * blockDim.x) {
        g_wt0[i]  = tf32r(W0[i]);
        g_wt1i[i] = tf32r(W1i[i]);
        g_wt1h[i] = tf32r(W1h[i]);
    }
}

// ---------------- precompute GEMM (f32x2, unchanged) --------------------------
__device__ __forceinline__ void ffma2(unsigned long long& d, unsigned long long a,
                                      unsigned long long b) {
    asm("fma.rn.f32x2 %0, %1, %2, %0;" : "+l"(d) : "l"(a), "l"(b));
}
__device__ __forceinline__ unsigned long long dupf(float a) {
    unsigned long long r; asm("mov.b64 %0, {%1, %1};" : "=l"(r) : "f"(a)); return r;
}
__device__ __forceinline__ float2 unpk(unsigned long long v) {
    float2 r; asm("mov.b64 {%0, %1}, %2;" : "=f"(r.x), "=f"(r.y) : "l"(v)); return r;
}

__global__ void __launch_bounds__(256)
pre_gemm_kernel(const float* __restrict__ X, const float* __restrict__ W,
                const float* __restrict__ bA, const float* __restrict__ bB)
{
    __shared__ float Xs[16][68];
    __shared__ float Ws[16][68];
    __shared__ float Ts[64 * 68];
    const int tid = threadIdx.x;
    const int bn  = blockIdx.x * 64;
    const int bm  = blockIdx.y * 64;
    const int tx  = tid & 15;
    const int ty  = tid >> 4;
    const int lm  = tid >> 2;
    const int lk  = (tid & 3) << 2;

    unsigned long long acc2[4][2];
#pragma unroll
    for (int i = 0; i < 4; i++) { acc2[i][0] = 0ull; acc2[i][1] = 0ull; }

    for (int k0 = 0; k0 < IN_DIM; k0 += 16) {
        float4 xa = *(const float4*)&X[(size_t)(bm + lm) * IN_DIM + k0 + lk];
        float4 wa = *(const float4*)&W[(size_t)(bn + lm) * IN_DIM + k0 + lk];
        __syncthreads();
        Xs[lk + 0][lm] = xa.x; Xs[lk + 1][lm] = xa.y; Xs[lk + 2][lm] = xa.z; Xs[lk + 3][lm] = xa.w;
        Ws[lk + 0][lm] = wa.x; Ws[lk + 1][lm] = wa.y; Ws[lk + 2][lm] = wa.z; Ws[lk + 3][lm] = wa.w;
        __syncthreads();
#pragma unroll
        for (int k = 0; k < 16; k++) {
            float4 av = *(const float4*)&Xs[k][ty << 2];
            ulonglong2 bv = *(const ulonglong2*)&Ws[k][tx << 2];
            unsigned long long a0 = dupf(av.x), a1 = dupf(av.y), a2 = dupf(av.z), a3 = dupf(av.w);
            ffma2(acc2[0][0], a0, bv.x); ffma2(acc2[0][1], a0, bv.y);
            ffma2(acc2[1][0], a1, bv.x); ffma2(acc2[1][1], a1, bv.y);
            ffma2(acc2[2][0], a2, bv.x); ffma2(acc2[2][1], a2, bv.y);
            ffma2(acc2[3][0], a3, bv.x); ffma2(acc2[3][1], a3, bv.y);
        }
    }

    float bb[4];
#pragma unroll
    for (int j = 0; j < 4; j++) { int n = bn + (tx << 2) + j; bb[j] = bA[n] + bB[n]; }

    __syncthreads();
#pragma unroll
    for (int i = 0; i < 4; i++) {
        float2 v01 = unpk(acc2[i][0]);
        float2 v23 = unpk(acc2[i][1]);
        int ml = (ty << 2) + i;
        Ts[((tx << 2) + 0) * 68 + ml] = v01.x + bb[0];
        Ts[((tx << 2) + 1) * 68 + ml] = v01.y + bb[1];
        Ts[((tx << 2) + 2) * 68 + ml] = v23.x + bb[2];
        Ts[((tx << 2) + 3) * 68 + ml] = v23.y + bb[3];
    }
    __syncthreads();

    const int tt = bm >> 7;
    const int b0 = bm & 127;
    const int nl = tid >> 2;
    const int mq = (tid & 3) << 4;
    float* dst = &g_pre0[((size_t)tt * G4H + bn + nl) * BATCH + b0 + mq];
    const float* src = &Ts[nl * 68 + mq];
#pragma unroll
    for (int s = 0; s < 4; s++)
        ((float4*)dst)[s] = ((const float4*)src)[s];
}

// ---------------- persistent tensor (mma.sync) LSTM ---------------------------
__device__ __forceinline__ void grid_bar(unsigned int phase) {
    __threadfence();
    __syncthreads();
    if (threadIdx.x == 0) {
        unsigned int arrived = atomicAdd(&g_bar_count, 1u) + 1u;
        if (arrived == (unsigned)NCTA * phase) {
            atomicExch(&g_bar_release, phase);
        } else {
            while (*(volatile unsigned int*)&g_bar_release < phase) { __nanosleep(64); }
        }
    }
    __syncthreads();
}

// prefetch registers for one chunk (per thread): A 8 x float4, B 4 x float4
struct Pf { float4 a[8]; float4 b[4]; };

__device__ __forceinline__ void ld_pf(Pf& pf, const float* __restrict__ srcA,
                                      const float* __restrict__ srcB, int kc,
                                      int B0, int u0, int tid)
{
#pragma unroll
    for (int it = 0; it < 8; it++) {
        const int idx = it * TPB + tid;
        const int m  = idx >> 5;                          // 0..63 local batch row
        const int kq = (idx & 31) << 2;
        pf.a[it] = __ldcg((const float4*)&srcA[(B0 + m) * HID + kc * 128 + kq]);
    }
#pragma unroll
    for (int it = 0; it < 4; it++) {
        const int idx = it * TPB + tid;
        const int r  = idx >> 5;                          // 0..31 gate row
        const int kq = (idx & 31) << 2;
        const int grow = (r >> 3) * HID + u0 + (r & 7);   // gate*HID + unit
        pf.b[it] = __ldg((const float4*)&srcB[(size_t)grow * HID + kc * 128 + kq]);
    }
}

__device__ __forceinline__ void sts_pf(char* sm, const Pf& pf, bool domask,
                                       const float* __restrict__ msm, int tid)
{
#pragma unroll
    for (int it = 0; it < 8; it++) {
        const int idx = it * TPB + tid;
        const int m  = idx >> 5;
        const int kq = (idx & 31) << 2;
        float4 v = pf.a[it];
        if (domask) { float s = msm[m]; v.x *= s; v.y *= s; v.z *= s; v.w *= s; }
        *(float4*)(sm + SM_A + m * 528 + kq * 4) = v;
    }
#pragma unroll
    for (int it = 0; it < 4; it++) {
        const int idx = it * TPB + tid;
        const int r  = idx >> 5;
        const int kq = (idx & 31) << 2;
        *(float4*)(sm + SM_B + r * 528 + kq * 4) = pf.b[it];
    }
}

// one 128-K chunk: warp covers m-tile mt (16 rows) x n-pair np (16 gate rows)
__device__ __forceinline__ void chunk_mma(float* acc, uint32_t aA, uint32_t bB)
{
#pragma unroll
    for (int ks = 0; ks < 16; ks++) {
        uint32_t af[4], bf[4];
        ldsm4(af, aA + ks * 32);
        ldsm4(bf, bB + ks * 32);
        mma_tf32(acc + 0, af, bf + 0);
        mma_tf32(acc + 4, af, bf + 2);
    }
}

__global__ void __launch_bounds__(TPB, 1)
lstm_kernel(const int* __restrict__ done,
            const float* __restrict__ c0_in,
            const float* __restrict__ b_ih1,
            const float* __restrict__ b_hh1,
            float* __restrict__ out_hT,
            float* __restrict__ out_cT)
{
    extern __shared__ char sm[];
    float* msm = (float*)(sm + SM_MSM);
    float* D_s = (float*)(sm + SM_A);      // D epilogue overlays A tile: [32 n][132]

    const int tid  = threadIdx.x;
    const int w    = tid >> 5;
    const int lane = tid & 31;
    const int bh   = blockIdx.x & 1;       // batch half
    const int B0   = bh * 64;
    const int u0   = (blockIdx.x >> 1) * NU;
    const int mt   = w >> 1;               // m-tile 0..3
    const int np   = w & 1;                // n-pair 0..1 (16 gate rows)

    // ldmatrix lane addresses (fixed for whole kernel)
    const uint32_t sb = smem_u32(sm);
    const int st = lane >> 3;
    const uint32_t aA = sb + SM_A + (mt * 16 + (st & 1) * 8 + (lane & 7)) * 528 + (st >> 1) * 16;
    const uint32_t bB = sb + SM_B + (np * 16 + (st >> 1) * 8 + (lane & 7)) * 528 + (st & 1) * 16;

    // cell-update thread mapping: local batch = tid&63, unit group = (tid>>6)*2
    const int bl = tid & 63;
    const int b  = B0 + bl;
    const int ug = (tid >> 6) * 2;

    float bias1[2][4];                     // [j][gate]
#pragma unroll
    for (int j = 0; j < 2; j++)
#pragma unroll
        for (int g = 0; g < 4; g++) {
            int row = g * HID + u0 + ug + j;
            bias1[j][g] = b_ih1[row] + b_hh1[row];
        }

    float c0r[2], c1r[2];
#pragma unroll
    for (int j = 0; j < 2; j++) {
        c0r[j] = c0_in[(0 * BATCH + b) * HID + u0 + ug + j];
        c1r[j] = c0_in[(1 * BATCH + b) * HID + u0 + ug + j];
    }

    unsigned int phase = 0;
    Pf pf;

    for (int t = 0; t < T_STEPS; t++) {
        const int p = t & 1;

        if (tid < 64) msm[tid] = 1.0f - (float)done[t * BATCH + B0 + tid];
        const float mk = 1.0f - (float)__ldg(&done[t * BATCH + b]);   // race-free mask

        // prefetch pre0 for this thread's 8 gate slots (used in epilogue 0)
        float pre[2][4];
#pragma unroll
        for (int j = 0; j < 2; j++)
#pragma unroll
            for (int g = 0; g < 4; g++)
                pre[j][g] = __ldcg(&g_pre0[((size_t)t * G4H + g * HID + u0 + ug + j) * BATCH + b]);

        // ================= layer 0: D = (h0*mask) @ W_hh0^T =================
        float acc[8];
#pragma unroll
        for (int i = 0; i < 8; i++) acc[i] = 0.f;

        ld_pf(pf, &g_h0[p][0][0], g_wt0, 0, B0, u0, tid);      // prime chunk 0
        for (int kc = 0; kc < 4; kc++) {
            __syncthreads();                                    // tile free
            sts_pf(sm, pf, true, msm, tid);
            if (kc + 1 < 4) ld_pf(pf, &g_h0[p][0][0], g_wt0, kc + 1, B0, u0, tid);
            __syncthreads();                                    // tile ready
            chunk_mma(acc, aA, bB);                             // overlaps next LDG
        }

        // epilogue 0: D -> smem -> cell update
        __syncthreads();
        {
            const int r = lane >> 2, c2 = (lane & 3) * 2;
#pragma unroll
            for (int nt = 0; nt < 2; nt++) {
                const int n = np * 16 + nt * 8 + c2;
                D_s[(n + 0) * 132 + mt * 16 + r]     = acc[nt * 4 + 0];
                D_s[(n + 1) * 132 + mt * 16 + r]     = acc[nt * 4 + 1];
                D_s[(n + 0) * 132 + mt * 16 + r + 8] = acc[nt * 4 + 2];
                D_s[(n + 1) * 132 + mt * 16 + r + 8] = acc[nt * 4 + 3];
            }
        }
        __syncthreads();
        {
#pragma unroll
            for (int j = 0; j < 2; j++) {
                const int u = ug + j;
                float gi = D_s[(0 * 8 + u) * 132 + bl] + pre[j][0];
                float gf = D_s[(1 * 8 + u) * 132 + bl] + pre[j][1];
                float gg = D_s[(2 * 8 + u) * 132 + bl] + pre[j][2];
                float go = D_s[(3 * 8 + u) * 132 + bl] + pre[j][3];
                float c  = fmaf(sigmoidf_(gf), c0r[j] * mk, sigmoidf_(gi) * tanhf(gg));
                c0r[j]   = c;
                g_h0[p ^ 1][b][u0 + u] = tf32r(sigmoidf_(go) * tanhf(c));
            }
        }

        grid_bar(++phase);

        // ========== layer 1: D = h0_new @ W_ih1^T + (h1*mask) @ W_hh1^T ==========
#pragma unroll
        for (int i = 0; i < 8; i++) acc[i] = 0.f;

        ld_pf(pf, &g_h0[p ^ 1][0][0], g_wt1i, 0, B0, u0, tid); // prime (after bar)
        for (int kc = 0; kc < 8; kc++) {
            __syncthreads();
            sts_pf(sm, pf, kc >= 4, msm, tid);
            if (kc + 1 < 8) {
                if (kc + 1 < 4) ld_pf(pf, &g_h0[p ^ 1][0][0], g_wt1i, kc + 1, B0, u0, tid);
                else            ld_pf(pf, &g_h1[p][0][0],     g_wt1h, (kc + 1) & 3, B0, u0, tid);
            }
            __syncthreads();
            chunk_mma(acc, aA, bB);
        }

        __syncthreads();
        {
            const int r = lane >> 2, c2 = (lane & 3) * 2;
#pragma unroll
            for (int nt = 0; nt < 2; nt++) {
                const int n = np * 16 + nt * 8 + c2;
                D_s[(n + 0) * 132 + mt * 16 + r]     = acc[nt * 4 + 0];
                D_s[(n + 1) * 132 + mt * 16 + r]     = acc[nt * 4 + 1];
                D_s[(n + 0) * 132 + mt * 16 + r + 8] = acc[nt * 4 + 2];
                D_s[(n + 1) * 132 + mt * 16 + r + 8] = acc[nt * 4 + 3];
            }
        }
        __syncthreads();
        {
#pragma unroll
            for (int j = 0; j < 2; j++) {
                const int u = ug + j;
                float gi = D_s[(0 * 8 + u) * 132 + bl] + bias1[j][0];
                float gf = D_s[(1 * 8 + u) * 132 + bl] + bias1[j][1];
                float gg = D_s[(2 * 8 + u) * 132 + bl] + bias1[j][2];
                float go = D_s[(3 * 8 + u) * 132 + bl] + bias1[j][3];
                float c  = fmaf(sigmoidf_(gf), c1r[j] * mk, sigmoidf_(gi) * tanhf(gg));
                c1r[j]   = c;
                float h  = tf32r(sigmoidf_(go) * tanhf(c));
                g_h1[p ^ 1][b][u0 + u] = h;
                g_hidden[((size_t)t * BATCH + b) * HID + u0 + u] = h;
            }
        }
        // one barrier per step: next step's grid_bar orders h1 for other CTAs
    }

    grid_bar(++phase);   // final writes visible before copy-out

#pragma unroll
    for (int j = 0; j < 2; j++) {
        out_cT[(0 * BATCH + b) * HID + u0 + ug + j] = c0r[j];
        out_cT[(1 * BATCH + b) * HID + u0 + ug + j] = c1r[j];
    }
    for (int i = blockIdx.x * TPB + tid; i < BATCH * HID; i += NCTA * TPB) {
        out_hT[i]               = __ldcg(&(&g_h0[0][0][0])[i]);
        out_hT[BATCH * HID + i] = __ldcg(&(&g_h1[0][0][0])[i]);
    }
}

// ---------------- actor/critic heads -----------------------------------------
__global__ void __launch_bounds__(256)
head_kernel(const float* __restrict__ Wa, const float* __restrict__ ba,
            const float* __restrict__ Wc, const float* __restrict__ bc,
            float* __restrict__ out)
{
    __shared__ float Ws[NACT * HID];
    __shared__ float bs[NACT];
    for (int i = threadIdx.x; i < 18 * HID; i += blockDim.x) Ws[i] = Wa[i];
    for (int i = threadIdx.x; i < HID; i += blockDim.x) Ws[18 * HID + i] = Wc[i];
    if (threadIdx.x < 18) bs[threadIdx.x] = ba[threadIdx.x];
    if (threadIdx.x == 18) bs[18] = bc[0];
    __syncthreads();

    const int warp = threadIdx.x >> 5;
    const int lane = threadIdx.x & 31;
    const size_t m = (size_t)blockIdx.x * 8 + warp;

    const float* hrow = &g_hidden[m * HID];
    float hv[16];
#pragma unroll
    for (int j = 0; j < 16; j++) hv[j] = hrow[lane + j * 32];

#pragma unroll
    for (int a = 0; a < NACT; a++) {
        float s = 0.f;
#pragma unroll
        for (int j = 0; j < 16; j++) s = fmaf(hv[j], Ws[a * HID + lane + j * 32], s);
#pragma unroll
        for (int off = 16; off > 0; off >>= 1) s += __shfl_xor_sync(0xffffffffu, s, off);
        if (lane == a) out[m * NACT + a] = s + bs[a];
    }
}

// ---------------- launch ------------------------------------------------------
extern "C" void kernel_launch(void* const* d_in, const int* in_sizes, int n_in,
                              void* d_out, int out_size)
{
    (void)in_sizes; (void)n_in; (void)out_size;
    const float* x     = (const float*)d_in[0];
    const int*   done  = (const int*)  d_in[1];
    const float* h0    = (const float*)d_in[2];
    const float* c0    = (const float*)d_in[3];
    const float* W_ih0 = (const float*)d_in[4];
    const float* W_hh0 = (const float*)d_in[5];
    const float* b_ih0 = (const float*)d_in[6];
    const float* b_hh0 = (const float*)d_in[7];
    const float* W_ih1 = (const float*)d_in[8];
    const float* W_hh1 = (const float*)d_in[9];
    const float* b_ih1 = (const float*)d_in[10];
    const float* b_hh1 = (const float*)d_in[11];
    const float* W_a   = (const float*)d_in[12];
    const float* b_a   = (const float*)d_in[13];
    const float* W_c   = (const float*)d_in[14];
    const float* b_c   = (const float*)d_in[15];

    float* out    = (float*)d_out;
    float* out_hT = out + (size_t)T_STEPS * BATCH * NACT;
    float* out_cT = out_hT + 2 * BATCH * HID;

    cudaFuncSetAttribute(lstm_kernel, cudaFuncAttributeMaxDynamicSharedMemorySize, SM_TOTAL);

    init_kernel<<<64, 256>>>(h0);
    wt_kernel<<<132, 256>>>(W_hh0, W_ih1, W_hh1);

    dim3 gg(G4H / 64, (T_STEPS * BATCH) / 64);
    pre_gemm_kernel<<<gg, 256>>>(x, W_ih0, b_ih0, b_hh0);

    lstm_kernel<<<NCTA, TPB, SM_TOTAL>>>(done, c0, b_ih1, b_hh1, out_hT, out_cT);

    head_kernel<<<(T_STEPS * BATCH) / 8, 256>>>(W_a, b_a, W_c, b_c, out);
}

// round 11
// speedup vs baseline: 4.4189x; 1.2579x over previous
#include <cuda_runtime.h>
#include <math.h>
#include <cstdint>

#define T_STEPS 512
#define BATCH   128
#define IN_DIM  544
#define HID     512
#define G4H     2048
#define NACT    19
#define NCTA    128     // CTA = (batch-half, unit-group of 8)
#define TPB     256     // 8 warps: warp = (m-tile 0..3, n-pair 0..1)
#define NU      8       // units per CTA (32 gate rows)

// LSTM SMEM: two (A 64x132 + B 32x132) buffers + masks
#define SM_AB    33792                        // B offset inside a buffer
#define SM_BUF   50688                        // buffer stride
#define SM_MSM   (2 * SM_BUF)                 // 101376
#define SM_TOTAL (SM_MSM + 512)

// pre-GEMM (mma) SMEM
#define PM_STR   140                          // floats per row (560 B, conflict-free)
#define PM_A     0
#define PM_B     (64 * PM_STR * 4)            // 35840
#define PM_BIAS  (PM_B + 128 * PM_STR * 4)    // 107520
#define PM_TOTAL (PM_BIAS + 512)

// ---------------- scratch ----------------------------------------------------
__device__ float g_pre0[(size_t)T_STEPS * G4H * BATCH];     // [t][n][b]
__device__ float g_hidden[(size_t)T_STEPS * BATCH * HID];
__device__ float g_h0[2][BATCH][HID];                       // tf32-rounded h
__device__ float g_h1[2][BATCH][HID];
__device__ float g_wt0[G4H * HID];                          // tf32-rounded weights
__device__ float g_wt1i[G4H * HID];
__device__ float g_wt1h[G4H * HID];
__device__ unsigned int g_bar_count;
__device__ unsigned int g_bar_release;

// ---------------- helpers ----------------------------------------------------
__device__ __forceinline__ uint32_t smem_u32(const void* p) {
    uint32_t a;
    asm("{ .reg .u64 t; cvta.to.shared.u64 t, %1; cvt.u32.u64 %0, t; }" : "=r"(a) : "l"(p));
    return a;
}
__device__ __forceinline__ float tf32r(float x) {
    uint32_t o; asm("cvt.rna.tf32.f32 %0, %1;" : "=r"(o) : "f"(x));
    return __uint_as_float(o);
}
__device__ __forceinline__ void ldsm4(uint32_t* r, uint32_t addr) {
    asm volatile("ldmatrix.sync.aligned.m8n8.x4.shared.b16 {%0,%1,%2,%3}, [%4];"
                 : "=r"(r[0]), "=r"(r[1]), "=r"(r[2]), "=r"(r[3]) : "r"(addr));
}
__device__ __forceinline__ void mma_tf32(float* d, const uint32_t* a, const uint32_t* b) {
    asm volatile("mma.sync.aligned.m16n8k8.row.col.f32.tf32.tf32.f32 "
                 "{%0,%1,%2,%3}, {%4,%5,%6,%7}, {%8,%9}, {%0,%1,%2,%3};"
                 : "+f"(d[0]), "+f"(d[1]), "+f"(d[2]), "+f"(d[3])
                 : "r"(a[0]), "r"(a[1]), "r"(a[2]), "r"(a[3]), "r"(b[0]), "r"(b[1]));
}
__device__ __forceinline__ float sigmoidf_(float x) { return 1.f / (1.f + expf(-x)); }

// ---------------- init / weight-round kernels --------------------------------
__global__ void init_kernel(const float* __restrict__ h0) {
    if (blockIdx.x == 0 && threadIdx.x == 0) { g_bar_count = 0u; g_bar_release = 0u; }
    const int n = BATCH * HID;
    for (int i = blockIdx.x * blockDim.x + threadIdx.x; i < n; i += gridDim.x * blockDim.x) {
        (&g_h0[0][0][0])[i] = tf32r(h0[i]);
        (&g_h1[0][0][0])[i] = tf32r(h0[n + i]);
    }
}

__global__ void wt_kernel(const float* __restrict__ W0, const float* __restrict__ W1i,
                          const float* __restrict__ W1h) {
    const int n = G4H * HID;
    for (int i = blockIdx.x * blockDim.x + threadIdx.x; i < n; i += gridDim.x * blockDim.x) {
        g_wt0[i]  = tf32r(W0[i]);
        g_wt1i[i] = tf32r(W1i[i]);
        g_wt1h[i] = tf32r(W1h[i]);
    }
}

// ---------------- pre-GEMM via tf32 mma ---------------------------------------
// g_pre0[t][n][b] = sum_k X[t*128+b, k] * W_ih0[n, k] + b_ih0[n] + b_hh0[n]
// CTA: 64 batch rows (half t-block) x 128 gate rows.  K = 544 = 4 chunks x 136.
__global__ void __launch_bounds__(256)
pre_mma_kernel(const float* __restrict__ X, const float* __restrict__ W,
               const float* __restrict__ bA, const float* __restrict__ bB)
{
    extern __shared__ char sm[];
    float* bias = (float*)(sm + PM_BIAS);
    float* D_s  = (float*)sm;              // epilogue overlays A/B: [128 n][68]

    const int tid  = threadIdx.x;
    const int w    = tid >> 5;
    const int lane = tid & 31;
    const int n0   = blockIdx.x * 128;
    const int row0 = blockIdx.y * 64;      // global X row base
    const int tt   = blockIdx.y >> 1;
    const int b0   = (blockIdx.y & 1) * 64;
    const int mt   = w >> 1;               // m-tile 0..3
    const int nh   = w & 1;                // n-half 0..1 (64 gate rows)

    if (tid < 128) bias[tid] = bA[n0 + tid] + bB[n0 + tid];

    const uint32_t sb = smem_u32(sm);
    const int st = lane >> 3;
    const uint32_t aA = sb + PM_A + (mt * 16 + (st & 1) * 8 + (lane & 7)) * 560 + (st >> 1) * 16;
    const uint32_t bBq = sb + PM_B + (nh * 64 + (st >> 1) * 8 + (lane & 7)) * 560 + (st & 1) * 16;

    float acc[32];
#pragma unroll
    for (int i = 0; i < 32; i++) acc[i] = 0.f;

    for (int kc = 0; kc < 4; kc++) {
        __syncthreads();
        // stage A: 64 rows x 34 float4 (tf32-rounded)
        {
            const int r = tid >> 2, q = tid & 3;
#pragma unroll
            for (int j = 0; j < 9; j++) {
                int c4 = j * 4 + q;
                if (c4 < 34) {
                    float4 v = __ldg((const float4*)&X[(size_t)(row0 + r) * IN_DIM + kc * 136 + c4 * 4]);
                    v.x = tf32r(v.x); v.y = tf32r(v.y); v.z = tf32r(v.z); v.w = tf32r(v.w);
                    *(float4*)(sm + PM_A + r * 560 + c4 * 16) = v;
                }
            }
        }
        // stage B: 128 rows x 34 float4
        {
            const int r = tid >> 1, q = tid & 1;
#pragma unroll
            for (int j = 0; j < 17; j++) {
                int c4 = j * 2 + q;
                float4 v = __ldg((const float4*)&W[(size_t)(n0 + r) * IN_DIM + kc * 136 + c4 * 4]);
                v.x = tf32r(v.x); v.y = tf32r(v.y); v.z = tf32r(v.z); v.w = tf32r(v.w);
                *(float4*)(sm + PM_B + r * 560 + c4 * 16) = v;
            }
        }
        __syncthreads();
#pragma unroll
        for (int ks = 0; ks < 17; ks++) {
            uint32_t af[4];
            ldsm4(af, aA + ks * 32);
#pragma unroll
            for (int nb = 0; nb < 4; nb++) {
                uint32_t bf[4];
                ldsm4(bf, bBq + nb * 16 * 560 + ks * 32);
                mma_tf32(acc + nb * 8 + 0, af, bf + 0);
                mma_tf32(acc + nb * 8 + 4, af, bf + 2);
            }
        }
    }

    // epilogue: D -> smem [n][68] -> transposed coalesced store + bias
    __syncthreads();
    {
        const int r = lane >> 2, c2 = (lane & 3) * 2;
#pragma unroll
        for (int nb = 0; nb < 4; nb++) {
            const int nbase = nh * 64 + nb * 16;
            D_s[(nbase + c2 + 0) * 68 + mt * 16 + r]     = acc[nb * 8 + 0];
            D_s[(nbase + c2 + 1) * 68 + mt * 16 + r]     = acc[nb * 8 + 1];
            D_s[(nbase + c2 + 0) * 68 + mt * 16 + r + 8] = acc[nb * 8 + 2];
            D_s[(nbase + c2 + 1) * 68 + mt * 16 + r + 8] = acc[nb * 8 + 3];
            D_s[(nbase + 8 + c2 + 0) * 68 + mt * 16 + r]     = acc[nb * 8 + 4];
            D_s[(nbase + 8 + c2 + 1) * 68 + mt * 16 + r]     = acc[nb * 8 + 5];
            D_s[(nbase + 8 + c2 + 0) * 68 + mt * 16 + r + 8] = acc[nb * 8 + 6];
            D_s[(nbase + 8 + c2 + 1) * 68 + mt * 16 + r + 8] = acc[nb * 8 + 7];
        }
    }
    __syncthreads();
    {
        const int n = tid >> 1, mh = tid & 1;
        const float bs = bias[n];
        float* dst = &g_pre0[((size_t)tt * G4H + n0 + n) * BATCH + b0 + mh * 32];
        const float* src = &D_s[n * 68 + mh * 32];
#pragma unroll
        for (int s = 0; s < 8; s++) {
            float4 v = ((const float4*)src)[s];
            ((float4*)dst)[s] = make_float4(v.x + bs, v.y + bs, v.z + bs, v.w + bs);
        }
    }
}

// ---------------- persistent tensor (mma.sync) LSTM ---------------------------
__device__ __forceinline__ void grid_bar(unsigned int phase) {
    __threadfence();
    __syncthreads();
    if (threadIdx.x == 0) {
        unsigned int arrived = atomicAdd(&g_bar_count, 1u) + 1u;
        if (arrived == (unsigned)NCTA * phase) {
            atomicExch(&g_bar_release, phase);
        } else {
            while (*(volatile unsigned int*)&g_bar_release < phase) { __nanosleep(64); }
        }
    }
    __syncthreads();
}

// prefetch registers for one chunk (per thread): A 8 x float4, B 4 x float4
struct Pf { float4 a[8]; float4 b[4]; };

__device__ __forceinline__ void ld_pf(Pf& pf, const float* __restrict__ srcA,
                                      const float* __restrict__ srcB, int kc,
                                      int B0, int u0, int tid)
{
#pragma unroll
    for (int it = 0; it < 8; it++) {
        const int idx = it * TPB + tid;
        const int m  = idx >> 5;
        const int kq = (idx & 31) << 2;
        pf.a[it] = __ldcg((const float4*)&srcA[(B0 + m) * HID + kc * 128 + kq]);
    }
#pragma unroll
    for (int it = 0; it < 4; it++) {
        const int idx = it * TPB + tid;
        const int r  = idx >> 5;
        const int kq = (idx & 31) << 2;
        const int grow = (r >> 3) * HID + u0 + (r & 7);
        pf.b[it] = __ldg((const float4*)&srcB[(size_t)grow * HID + kc * 128 + kq]);
    }
}

__device__ __forceinline__ void sts_pf(char* sm, int base, const Pf& pf, bool domask,
                                       const float* __restrict__ msm, int tid)
{
#pragma unroll
    for (int it = 0; it < 8; it++) {
        const int idx = it * TPB + tid;
        const int m  = idx >> 5;
        const int kq = (idx & 31) << 2;
        float4 v = pf.a[it];
        if (domask) { float s = msm[m]; v.x *= s; v.y *= s; v.z *= s; v.w *= s; }
        *(float4*)(sm + base + m * 528 + kq * 4) = v;
    }
#pragma unroll
    for (int it = 0; it < 4; it++) {
        const int idx = it * TPB + tid;
        const int r  = idx >> 5;
        const int kq = (idx & 31) << 2;
        *(float4*)(sm + base + SM_AB + r * 528 + kq * 4) = pf.b[it];
    }
}

__device__ __forceinline__ void chunk_mma(float* acc, uint32_t aA, uint32_t bB)
{
#pragma unroll
    for (int ks = 0; ks < 16; ks++) {
        uint32_t af[4], bf[4];
        ldsm4(af, aA + ks * 32);
        ldsm4(bf, bB + ks * 32);
        mma_tf32(acc + 0, af, bf + 0);
        mma_tf32(acc + 4, af, bf + 2);
    }
}

__global__ void __launch_bounds__(TPB, 1)
lstm_kernel(const int* __restrict__ done,
            const float* __restrict__ c0_in,
            const float* __restrict__ b_ih1,
            const float* __restrict__ b_hh1,
            float* __restrict__ out_hT,
            float* __restrict__ out_cT)
{
    extern __shared__ char sm[];
    float* msm = (float*)(sm + SM_MSM);
    float* D_s = (float*)sm;               // epilogue overlays buffer 0 A tile

    const int tid  = threadIdx.x;
    const int w    = tid >> 5;
    const int lane = tid & 31;
    const int bh   = blockIdx.x & 1;
    const int B0   = bh * 64;
    const int u0   = (blockIdx.x >> 1) * NU;
    const int mt   = w >> 1;
    const int np   = w & 1;

    const uint32_t sb = smem_u32(sm);
    const int st = lane >> 3;
    const uint32_t aOff = (mt * 16 + (st & 1) * 8 + (lane & 7)) * 528 + (st >> 1) * 16;
    const uint32_t bOff = SM_AB + (np * 16 + (st >> 1) * 8 + (lane & 7)) * 528 + (st & 1) * 16;
    const uint32_t aA0 = sb + aOff,          bB0 = sb + bOff;
    const uint32_t aA1 = sb + SM_BUF + aOff, bB1 = sb + SM_BUF + bOff;

    const int bl = tid & 63;
    const int b  = B0 + bl;
    const int ug = (tid >> 6) * 2;

    float bias1[2][4];
#pragma unroll
    for (int j = 0; j < 2; j++)
#pragma unroll
        for (int g = 0; g < 4; g++) {
            int row = g * HID + u0 + ug + j;
            bias1[j][g] = b_ih1[row] + b_hh1[row];
        }

    float c0r[2], c1r[2];
#pragma unroll
    for (int j = 0; j < 2; j++) {
        c0r[j] = c0_in[(0 * BATCH + b) * HID + u0 + ug + j];
        c1r[j] = c0_in[(1 * BATCH + b) * HID + u0 + ug + j];
    }

    unsigned int phase = 0;
    Pf pf;

    for (int t = 0; t < T_STEPS; t++) {
        const int p = t & 1;

        if (tid < 64) msm[tid] = 1.0f - (float)done[t * BATCH + B0 + tid];
        const float mk = 1.0f - (float)__ldg(&done[t * BATCH + b]);

        float pre[2][4];
#pragma unroll
        for (int j = 0; j < 2; j++)
#pragma unroll
            for (int g = 0; g < 4; g++)
                pre[j][g] = __ldcg(&g_pre0[((size_t)t * G4H + g * HID + u0 + ug + j) * BATCH + b]);

        __syncthreads();   // msm visible; prev step's D_s reads done

        // ===== layer 0: D = (h0*mask) @ W_hh0^T  (4 chunks, double-buffered) =====
        float acc[8];
#pragma unroll
        for (int i = 0; i < 8; i++) acc[i] = 0.f;

        ld_pf(pf, &g_h0[p][0][0], g_wt0, 0, B0, u0, tid);
        sts_pf(sm, 0, pf, true, msm, tid);
        ld_pf(pf, &g_h0[p][0][0], g_wt0, 1, B0, u0, tid);
#pragma unroll
        for (int kc = 0; kc < 4; kc++) {
            __syncthreads();                               // buf[kc&1] ready
            if (kc + 1 < 4) sts_pf(sm, (kc + 1) & 1 ? SM_BUF : 0, pf, true, msm, tid);
            if (kc + 2 < 4) ld_pf(pf, &g_h0[p][0][0], g_wt0, kc + 2, B0, u0, tid);
            chunk_mma(acc, (kc & 1) ? aA1 : aA0, (kc & 1) ? bB1 : bB0);
        }

        // epilogue 0 (D_s = buf0-A; last chunk used buf1 — no extra sync needed)
        {
            const int r = lane >> 2, c2 = (lane & 3) * 2;
#pragma unroll
            for (int nt = 0; nt < 2; nt++) {
                const int n = np * 16 + nt * 8 + c2;
                D_s[(n + 0) * 132 + mt * 16 + r]     = acc[nt * 4 + 0];
                D_s[(n + 1) * 132 + mt * 16 + r]     = acc[nt * 4 + 1];
                D_s[(n + 0) * 132 + mt * 16 + r + 8] = acc[nt * 4 + 2];
                D_s[(n + 1) * 132 + mt * 16 + r + 8] = acc[nt * 4 + 3];
            }
        }
        __syncthreads();
        {
#pragma unroll
            for (int j = 0; j < 2; j++) {
                const int u = ug + j;
                float gi = D_s[(0 * 8 + u) * 132 + bl] + pre[j][0];
                float gf = D_s[(1 * 8 + u) * 132 + bl] + pre[j][1];
                float gg = D_s[(2 * 8 + u) * 132 + bl] + pre[j][2];
                float go = D_s[(3 * 8 + u) * 132 + bl] + pre[j][3];
                float c  = fmaf(sigmoidf_(gf), c0r[j] * mk, sigmoidf_(gi) * tanhf(gg));
                c0r[j]   = c;
                g_h0[p ^ 1][b][u0 + u] = tf32r(sigmoidf_(go) * tanhf(c));
            }
        }

        grid_bar(++phase);

        // ===== layer 1: D = h0_new @ W_ih1^T + (h1*mask) @ W_hh1^T (8 chunks) =====
#pragma unroll
        for (int i = 0; i < 8; i++) acc[i] = 0.f;

        ld_pf(pf, &g_h0[p ^ 1][0][0], g_wt1i, 0, B0, u0, tid);
        sts_pf(sm, 0, pf, false, msm, tid);
        ld_pf(pf, &g_h0[p ^ 1][0][0], g_wt1i, 1, B0, u0, tid);
#pragma unroll
        for (int kc = 0; kc < 8; kc++) {
            __syncthreads();
            if (kc + 1 < 8) sts_pf(sm, (kc + 1) & 1 ? SM_BUF : 0, pf, (kc + 1) >= 4, msm, tid);
            if (kc + 2 < 8) {
                if (kc + 2 < 4) ld_pf(pf, &g_h0[p ^ 1][0][0], g_wt1i, kc + 2, B0, u0, tid);
                else            ld_pf(pf, &g_h1[p][0][0],     g_wt1h, (kc + 2) & 3, B0, u0, tid);
            }
            chunk_mma(acc, (kc & 1) ? aA1 : aA0, (kc & 1) ? bB1 : bB0);
        }

        {
            const int r = lane >> 2, c2 = (lane & 3) * 2;
#pragma unroll
            for (int nt = 0; nt < 2; nt++) {
                const int n = np * 16 + nt * 8 + c2;
                D_s[(n + 0) * 132 + mt * 16 + r]     = acc[nt * 4 + 0];
                D_s[(n + 1) * 132 + mt * 16 + r]     = acc[nt * 4 + 1];
                D_s[(n + 0) * 132 + mt * 16 + r + 8] = acc[nt * 4 + 2];
                D_s[(n + 1) * 132 + mt * 16 + r + 8] = acc[nt * 4 + 3];
            }
        }
        __syncthreads();
        {
#pragma unroll
            for (int j = 0; j < 2; j++) {
                const int u = ug + j;
                float gi = D_s[(0 * 8 + u) * 132 + bl] + bias1[j][0];
                float gf = D_s[(1 * 8 + u) * 132 + bl] + bias1[j][1];
                float gg = D_s[(2 * 8 + u) * 132 + bl] + bias1[j][2];
                float go = D_s[(3 * 8 + u) * 132 + bl] + bias1[j][3];
                float c  = fmaf(sigmoidf_(gf), c1r[j] * mk, sigmoidf_(gi) * tanhf(gg));
                c1r[j]   = c;
                float h  = tf32r(sigmoidf_(go) * tanhf(c));
                g_h1[p ^ 1][b][u0 + u] = h;
                g_hidden[((size_t)t * BATCH + b) * HID + u0 + u] = h;
            }
        }
        // next step's top sync + grid_bar order everything else
    }

    grid_bar(++phase);

#pragma unroll
    for (int j = 0; j < 2; j++) {
        out_cT[(0 * BATCH + b) * HID + u0 + ug + j] = c0r[j];
        out_cT[(1 * BATCH + b) * HID + u0 + ug + j] = c1r[j];
    }
    for (int i = blockIdx.x * TPB + tid; i < BATCH * HID; i += NCTA * TPB) {
        out_hT[i]               = __ldcg(&(&g_h0[0][0][0])[i]);
        out_hT[BATCH * HID + i] = __ldcg(&(&g_h1[0][0][0])[i]);
    }
}

// ---------------- actor/critic heads -----------------------------------------
__global__ void __launch_bounds__(256)
head_kernel(const float* __restrict__ Wa, const float* __restrict__ ba,
            const float* __restrict__ Wc, const float* __restrict__ bc,
            float* __restrict__ out)
{
    __shared__ float Ws[NACT * HID];
    __shared__ float bs[NACT];
    for (int i = threadIdx.x; i < 18 * HID; i += blockDim.x) Ws[i] = Wa[i];
    for (int i = threadIdx.x; i < HID; i += blockDim.x) Ws[18 * HID + i] = Wc[i];
    if (threadIdx.x < 18) bs[threadIdx.x] = ba[threadIdx.x];
    if (threadIdx.x == 18) bs[18] = bc[0];
    __syncthreads();

    const int warp = threadIdx.x >> 5;
    const int lane = threadIdx.x & 31;
    const size_t m = (size_t)blockIdx.x * 8 + warp;

    const float* hrow = &g_hidden[m * HID];
    float hv[16];
#pragma unroll
    for (int j = 0; j < 16; j++) hv[j] = hrow[lane + j * 32];

#pragma unroll
    for (int a = 0; a < NACT; a++) {
        float s = 0.f;
#pragma unroll
        for (int j = 0; j < 16; j++) s = fmaf(hv[j], Ws[a * HID + lane + j * 32], s);
#pragma unroll
        for (int off = 16; off > 0; off >>= 1) s += __shfl_xor_sync(0xffffffffu, s, off);
        if (lane == a) out[m * NACT + a] = s + bs[a];
    }
}

// ---------------- launch ------------------------------------------------------
extern "C" void kernel_launch(void* const* d_in, const int* in_sizes, int n_in,
                              void* d_out, int out_size)
{
    (void)in_sizes; (void)n_in; (void)out_size;
    const float* x     = (const float*)d_in[0];
    const int*   done  = (const int*)  d_in[1];
    const float* h0    = (const float*)d_in[2];
    const float* c0    = (const float*)d_in[3];
    const float* W_ih0 = (const float*)d_in[4];
    const float* W_hh0 = (const float*)d_in[5];
    const float* b_ih0 = (const float*)d_in[6];
    const float* b_hh0 = (const float*)d_in[7];
    const float* W_ih1 = (const float*)d_in[8];
    const float* W_hh1 = (const float*)d_in[9];
    const float* b_ih1 = (const float*)d_in[10];
    const float* b_hh1 = (const float*)d_in[11];
    const float* W_a   = (const float*)d_in[12];
    const float* b_a   = (const float*)d_in[13];
    const float* W_c   = (const float*)d_in[14];
    const float* b_c   = (const float*)d_in[15];

    float* out    = (float*)d_out;
    float* out_hT = out + (size_t)T_STEPS * BATCH * NACT;
    float* out_cT = out_hT + 2 * BATCH * HID;

    cudaFuncSetAttribute(lstm_kernel, cudaFuncAttributeMaxDynamicSharedMemorySize, SM_TOTAL);
    cudaFuncSetAttribute(pre_mma_kernel, cudaFuncAttributeMaxDynamicSharedMemorySize, PM_TOTAL);

    init_kernel<<<64, 256>>>(h0);
    wt_kernel<<<132, 256>>>(W_hh0, W_ih1, W_hh1);

    dim3 gg(G4H / 128, (T_STEPS * BATCH) / 64);
    pre_mma_kernel<<<gg, 256, PM_TOTAL>>>(x, W_ih0, b_ih0, b_hh0);

    lstm_kernel<<<NCTA, TPB, SM_TOTAL>>>(done, c0, b_ih1, b_hh1, out_hT, out_cT);

    head_kernel<<<(T_STEPS * BATCH) / 8, 256>>>(W_a, b_a, W_c, b_c, out);
}

// round 13
// speedup vs baseline: 4.6371x; 1.0494x over previous
#include <cuda_runtime.h>
#include <math.h>
#include <cstdint>

#define T_STEPS 512
#define BATCH   128
#define IN_DIM  544
#define HID     512
#define G4H     2048
#define NACT    19
#define NCTA    128     // CTA = (batch-half, unit-group of 8)
#define TPB     256     // 8 warps: warp = (m-tile 0..3, n-pair 0..1)
#define NU      8       // units per CTA (32 gate rows)

// LSTM SMEM: three (A 64x132 + B 32x132) circular buffers
#define SM_AB    33792                        // B offset inside a buffer
#define SM_BUF   50688                        // buffer stride
#define SM_TOTAL (3 * SM_BUF)                 // 152064

// pre-GEMM (mma) SMEM
#define PM_STR   140
#define PM_A     0
#define PM_B     (64 * PM_STR * 4)
#define PM_BIAS  (PM_B + 128 * PM_STR * 4)
#define PM_TOTAL (PM_BIAS + 512)

// ---------------- scratch ----------------------------------------------------
__device__ float g_pre0[(size_t)T_STEPS * G4H * BATCH];     // [t][n][b]
__device__ float g_hidden[(size_t)T_STEPS * BATCH * HID];
__device__ float g_h0[2][BATCH][HID];                       // tf32-rounded h
__device__ float g_h1[2][BATCH][HID];
__device__ float g_wt0[G4H * HID];                          // tf32-rounded weights
__device__ float g_wt1i[G4H * HID];
__device__ float g_wt1h[G4H * HID];
__device__ unsigned int g_bar_count;
__device__ unsigned int g_bar_release;

// ---------------- helpers ----------------------------------------------------
__device__ __forceinline__ uint32_t smem_u32(const void* p) {
    uint32_t a;
    asm("{ .reg .u64 t; cvta.to.shared.u64 t, %1; cvt.u32.u64 %0, t; }" : "=r"(a) : "l"(p));
    return a;
}
__device__ __forceinline__ float tf32r(float x) {
    uint32_t o; asm("cvt.rna.tf32.f32 %0, %1;" : "=r"(o) : "f"(x));
    return __uint_as_float(o);
}
__device__ __forceinline__ void ldsm4(uint32_t* r, uint32_t addr) {
    asm volatile("ldmatrix.sync.aligned.m8n8.x4.shared.b16 {%0,%1,%2,%3}, [%4];"
                 : "=r"(r[0]), "=r"(r[1]), "=r"(r[2]), "=r"(r[3]) : "r"(addr));
}
__device__ __forceinline__ void mma_tf32(float* d, const uint32_t* a, const uint32_t* b) {
    asm volatile("mma.sync.aligned.m16n8k8.row.col.f32.tf32.tf32.f32 "
                 "{%0,%1,%2,%3}, {%4,%5,%6,%7}, {%8,%9}, {%0,%1,%2,%3};"
                 : "+f"(d[0]), "+f"(d[1]), "+f"(d[2]), "+f"(d[3])
                 : "r"(a[0]), "r"(a[1]), "r"(a[2]), "r"(a[3]), "r"(b[0]), "r"(b[1]));
}
__device__ __forceinline__ void cp16cg(uint32_t d, const void* s) {
    asm volatile("cp.async.cg.shared.global [%0], [%1], 16;" :: "r"(d), "l"(s));
}
__device__ __forceinline__ void cp16ca(uint32_t d, const void* s) {
    asm volatile("cp.async.ca.shared.global [%0], [%1], 16;" :: "r"(d), "l"(s));
}
#define CP_COMMIT() asm volatile("cp.async.commit_group;" ::: "memory")
#define CP_WAIT1()  asm volatile("cp.async.wait_group 1;" ::: "memory")
__device__ __forceinline__ float sigmoidf_(float x) { return 1.f / (1.f + expf(-x)); }

// ---------------- init / weight-round kernels --------------------------------
__global__ void init_kernel(const float* __restrict__ h0) {
    if (blockIdx.x == 0 && threadIdx.x == 0) { g_bar_count = 0u; g_bar_release = 0u; }
    const int n = BATCH * HID;
    for (int i = blockIdx.x * blockDim.x + threadIdx.x; i < n; i += gridDim.x * blockDim.x) {
        (&g_h0[0][0][0])[i] = tf32r(h0[i]);
        (&g_h1[0][0][0])[i] = tf32r(h0[n + i]);
    }
}

__global__ void wt_kernel(const float* __restrict__ W0, const float* __restrict__ W1i,
                          const float* __restrict__ W1h) {
    const int n = G4H * HID;
    for (int i = blockIdx.x * blockDim.x + threadIdx.x; i < n; i += gridDim.x * blockDim.x) {
        g_wt0[i]  = tf32r(W0[i]);
        g_wt1i[i] = tf32r(W1i[i]);
        g_wt1h[i] = tf32r(W1h[i]);
    }
}

// ---------------- pre-GEMM via tf32 mma (unchanged from R11) ------------------
__global__ void __launch_bounds__(256)
pre_mma_kernel(const float* __restrict__ X, const float* __restrict__ W,
               const float* __restrict__ bA, const float* __restrict__ bB)
{
    extern __shared__ char sm[];
    float* bias = (float*)(sm + PM_BIAS);
    float* D_s  = (float*)sm;

    const int tid  = threadIdx.x;
    const int w    = tid >> 5;
    const int lane = tid & 31;
    const int n0   = blockIdx.x * 128;
    const int row0 = blockIdx.y * 64;
    const int tt   = blockIdx.y >> 1;
    const int b0   = (blockIdx.y & 1) * 64;
    const int mt   = w >> 1;
    const int nh   = w & 1;

    if (tid < 128) bias[tid] = bA[n0 + tid] + bB[n0 + tid];

    const uint32_t sb = smem_u32(sm);
    const int st = lane >> 3;
    const uint32_t aA = sb + PM_A + (mt * 16 + (st & 1) * 8 + (lane & 7)) * 560 + (st >> 1) * 16;
    const uint32_t bBq = sb + PM_B + (nh * 64 + (st >> 1) * 8 + (lane & 7)) * 560 + (st & 1) * 16;

    float acc[32];
#pragma unroll
    for (int i = 0; i < 32; i++) acc[i] = 0.f;

    for (int kc = 0; kc < 4; kc++) {
        __syncthreads();
        {
            const int r = tid >> 2, q = tid & 3;
#pragma unroll
            for (int j = 0; j < 9; j++) {
                int c4 = j * 4 + q;
                if (c4 < 34) {
                    float4 v = __ldg((const float4*)&X[(size_t)(row0 + r) * IN_DIM + kc * 136 + c4 * 4]);
                    v.x = tf32r(v.x); v.y = tf32r(v.y); v.z = tf32r(v.z); v.w = tf32r(v.w);
                    *(float4*)(sm + PM_A + r * 560 + c4 * 16) = v;
                }
            }
        }
        {
            const int r = tid >> 1, q = tid & 1;
#pragma unroll
            for (int j = 0; j < 17; j++) {
                int c4 = j * 2 + q;
                float4 v = __ldg((const float4*)&W[(size_t)(n0 + r) * IN_DIM + kc * 136 + c4 * 4]);
                v.x = tf32r(v.x); v.y = tf32r(v.y); v.z = tf32r(v.z); v.w = tf32r(v.w);
                *(float4*)(sm + PM_B + r * 560 + c4 * 16) = v;
            }
        }
        __syncthreads();
#pragma unroll
        for (int ks = 0; ks < 17; ks++) {
            uint32_t af[4];
            ldsm4(af, aA + ks * 32);
#pragma unroll
            for (int nb = 0; nb < 4; nb++) {
                uint32_t bf[4];
                ldsm4(bf, bBq + nb * 16 * 560 + ks * 32);
                mma_tf32(acc + nb * 8 + 0, af, bf + 0);
                mma_tf32(acc + nb * 8 + 4, af, bf + 2);
            }
        }
    }

    __syncthreads();
    {
        const int r = lane >> 2, c2 = (lane & 3) * 2;
#pragma unroll
        for (int nb = 0; nb < 4; nb++) {
            const int nbase = nh * 64 + nb * 16;
            D_s[(nbase + c2 + 0) * 68 + mt * 16 + r]     = acc[nb * 8 + 0];
            D_s[(nbase + c2 + 1) * 68 + mt * 16 + r]     = acc[nb * 8 + 1];
            D_s[(nbase + c2 + 0) * 68 + mt * 16 + r + 8] = acc[nb * 8 + 2];
            D_s[(nbase + c2 + 1) * 68 + mt * 16 + r + 8] = acc[nb * 8 + 3];
            D_s[(nbase + 8 + c2 + 0) * 68 + mt * 16 + r]     = acc[nb * 8 + 4];
            D_s[(nbase + 8 + c2 + 1) * 68 + mt * 16 + r]     = acc[nb * 8 + 5];
            D_s[(nbase + 8 + c2 + 0) * 68 + mt * 16 + r + 8] = acc[nb * 8 + 6];
            D_s[(nbase + 8 + c2 + 1) * 68 + mt * 16 + r + 8] = acc[nb * 8 + 7];
        }
    }
    __syncthreads();
    {
        const int n = tid >> 1, mh = tid & 1;
        const float bs = bias[n];
        float* dst = &g_pre0[((size_t)tt * G4H + n0 + n) * BATCH + b0 + mh * 32];
        const float* src = &D_s[n * 68 + mh * 32];
#pragma unroll
        for (int s = 0; s < 8; s++) {
            float4 v = ((const float4*)src)[s];
            ((float4*)dst)[s] = make_float4(v.x + bs, v.y + bs, v.z + bs, v.w + bs);
        }
    }
}

// ---------------- persistent tensor (mma.sync + cp.async) LSTM ----------------
__device__ __forceinline__ void grid_bar(unsigned int phase) {
    __threadfence();
    __syncthreads();
    if (threadIdx.x == 0) {
        unsigned int arrived = atomicAdd(&g_bar_count, 1u) + 1u;
        if (arrived == (unsigned)NCTA * phase) {
            atomicExch(&g_bar_release, phase);
        } else {
            while (*(volatile unsigned int*)&g_bar_release < phase) { __nanosleep(64); }
        }
    }
    __syncthreads();
}

// issue async stage of one chunk into buffer 'buf' (no transform; mask in epilogue)
__device__ __forceinline__ void stage_async(uint32_t sbuf,
                                            const float* __restrict__ srcA,
                                            const float* __restrict__ srcB,
                                            int kc, int B0, int u0, int tid)
{
#pragma unroll
    for (int it = 0; it < 8; it++) {
        const int idx = it * TPB + tid;
        const int m  = idx >> 5;
        const int kq = (idx & 31) << 2;
        cp16cg(sbuf + m * 528 + kq * 4, &srcA[(B0 + m) * HID + kc * 128 + kq]);
    }
#pragma unroll
    for (int it = 0; it < 4; it++) {
        const int idx = it * TPB + tid;
        const int r  = idx >> 5;
        const int kq = (idx & 31) << 2;
        const int grow = (r >> 3) * HID + u0 + (r & 7);
        cp16ca(sbuf + SM_AB + r * 528 + kq * 4, &srcB[(size_t)grow * HID + kc * 128 + kq]);
    }
}

__device__ __forceinline__ void chunk_mma(float* acc, uint32_t aA, uint32_t bB)
{
#pragma unroll
    for (int ks = 0; ks < 16; ks++) {
        uint32_t af[4], bf[4];
        ldsm4(af, aA + ks * 32);
        ldsm4(bf, bB + ks * 32);
        mma_tf32(acc + 0, af, bf + 0);
        mma_tf32(acc + 4, af, bf + 2);
    }
}

__global__ void __launch_bounds__(TPB, 1)
lstm_kernel(const int* __restrict__ done,
            const float* __restrict__ c0_in,
            const float* __restrict__ b_ih1,
            const float* __restrict__ b_hh1,
            float* __restrict__ out_hT,
            float* __restrict__ out_cT)
{
    extern __shared__ char sm[];
    float* D_s  = (float*)sm;              // layer0 D / layer1 D_ih (overlays buf0 A)
    float* D_hh = (float*)(sm + 16896);    // layer1 D_hh (second half of buf0 A)

    const int tid  = threadIdx.x;
    const int w    = tid >> 5;
    const int lane = tid & 31;
    const int bh   = blockIdx.x & 1;
    const int B0   = bh * 64;
    const int u0   = (blockIdx.x >> 1) * NU;
    const int mt   = w >> 1;
    const int np   = w & 1;

    const uint32_t sb = smem_u32(sm);
    const int st = lane >> 3;
    const uint32_t aOff = (mt * 16 + (st & 1) * 8 + (lane & 7)) * 528 + (st >> 1) * 16;
    const uint32_t bOff = SM_AB + (np * 16 + (st >> 1) * 8 + (lane & 7)) * 528 + (st & 1) * 16;

    const int bl = tid & 63;
    const int b  = B0 + bl;
    const int ug = (tid >> 6) * 2;

    float bias1[2][4];
#pragma unroll
    for (int j = 0; j < 2; j++)
#pragma unroll
        for (int g = 0; g < 4; g++) {
            int row = g * HID + u0 + ug + j;
            bias1[j][g] = b_ih1[row] + b_hh1[row];
        }

    float c0r[2], c1r[2];
#pragma unroll
    for (int j = 0; j < 2; j++) {
        c0r[j] = c0_in[(0 * BATCH + b) * HID + u0 + ug + j];
        c1r[j] = c0_in[(1 * BATCH + b) * HID + u0 + ug + j];
    }

    unsigned int phase = 0;

    for (int t = 0; t < T_STEPS; t++) {
        const int p = t & 1;
        const float mk = 1.0f - (float)__ldg(&done[t * BATCH + b]);

        float pre[2][4];
#pragma unroll
        for (int j = 0; j < 2; j++)
#pragma unroll
            for (int g = 0; g < 4; g++)
                pre[j][g] = __ldcg(&g_pre0[((size_t)t * G4H + g * HID + u0 + ug + j) * BATCH + b]);

        __syncthreads();   // prior epilogue D_s reads complete (buf0 reuse)

        // ===== layer 0: D = h0 @ W_hh0^T (mask applied in epilogue) =====
        const float* hA0 = &g_h0[p][0][0];
        float acc[8];
#pragma unroll
        for (int i = 0; i < 8; i++) acc[i] = 0.f;

        stage_async(sb + 0 * SM_BUF, hA0, g_wt0, 0, B0, u0, tid); CP_COMMIT();
        stage_async(sb + 1 * SM_BUF, hA0, g_wt0, 1, B0, u0, tid); CP_COMMIT();
#pragma unroll
        for (int kc = 0; kc < 4; kc++) {
            CP_WAIT1();
            __syncthreads();
            if (kc + 2 < 4) stage_async(sb + ((kc + 2) % 3) * SM_BUF, hA0, g_wt0, kc + 2, B0, u0, tid);
            CP_COMMIT();
            chunk_mma(acc, sb + (kc % 3) * SM_BUF + aOff, sb + (kc % 3) * SM_BUF + bOff);
        }

        __syncthreads();   // all warps done reading buf0 (chunk 3) before D_s overlay
        {
            const int r = lane >> 2, c2 = (lane & 3) * 2;
#pragma unroll
            for (int nt = 0; nt < 2; nt++) {
                const int n = np * 16 + nt * 8 + c2;
                D_s[(n + 0) * 132 + mt * 16 + r]     = acc[nt * 4 + 0];
                D_s[(n + 1) * 132 + mt * 16 + r]     = acc[nt * 4 + 1];
                D_s[(n + 0) * 132 + mt * 16 + r + 8] = acc[nt * 4 + 2];
                D_s[(n + 1) * 132 + mt * 16 + r + 8] = acc[nt * 4 + 3];
            }
        }
        __syncthreads();
        {
#pragma unroll
            for (int j = 0; j < 2; j++) {
                const int u = ug + j;
                float gi = fmaf(mk, D_s[(0 * 8 + u) * 132 + bl], pre[j][0]);
                float gf = fmaf(mk, D_s[(1 * 8 + u) * 132 + bl], pre[j][1]);
                float gg = fmaf(mk, D_s[(2 * 8 + u) * 132 + bl], pre[j][2]);
                float go = fmaf(mk, D_s[(3 * 8 + u) * 132 + bl], pre[j][3]);
                float c  = fmaf(sigmoidf_(gf), c0r[j] * mk, sigmoidf_(gi) * tanhf(gg));
                c0r[j]   = c;
                g_h0[p ^ 1][b][u0 + u] = tf32r(sigmoidf_(go) * tanhf(c));
            }
        }

        grid_bar(++phase);

        // ===== layer 1: D_ih = h0_new @ W_ih1^T ; D_hh = h1 @ W_hh1^T =====
        const float* hA1i = &g_h0[p ^ 1][0][0];
        const float* hA1h = &g_h1[p][0][0];
        float accI[8], accH[8];
#pragma unroll
        for (int i = 0; i < 8; i++) { accI[i] = 0.f; accH[i] = 0.f; }

        stage_async(sb + 0 * SM_BUF, hA1i, g_wt1i, 0, B0, u0, tid); CP_COMMIT();
        stage_async(sb + 1 * SM_BUF, hA1i, g_wt1i, 1, B0, u0, tid); CP_COMMIT();
#pragma unroll
        for (int kc = 0; kc < 8; kc++) {
            CP_WAIT1();
            __syncthreads();
            if (kc + 2 < 8) {
                const int kcc = kc + 2;
                stage_async(sb + (kcc % 3) * SM_BUF,
                            (kcc < 4) ? hA1i : hA1h,
                            (kcc < 4) ? g_wt1i : g_wt1h,
                            kcc & 3, B0, u0, tid);
            }
            CP_COMMIT();
            chunk_mma((kc < 4) ? accI : accH,
                      sb + (kc % 3) * SM_BUF + aOff, sb + (kc % 3) * SM_BUF + bOff);
        }

        __syncthreads();   // safe overlay of buf0 by D_ih/D_hh
        {
            const int r = lane >> 2, c2 = (lane & 3) * 2;
#pragma unroll
            for (int nt = 0; nt < 2; nt++) {
                const int n = np * 16 + nt * 8 + c2;
                D_s [(n + 0) * 132 + mt * 16 + r]     = accI[nt * 4 + 0];
                D_s [(n + 1) * 132 + mt * 16 + r]     = accI[nt * 4 + 1];
                D_s [(n + 0) * 132 + mt * 16 + r + 8] = accI[nt * 4 + 2];
                D_s [(n + 1) * 132 + mt * 16 + r + 8] = accI[nt * 4 + 3];
                D_hh[(n + 0) * 132 + mt * 16 + r]     = accH[nt * 4 + 0];
                D_hh[(n + 1) * 132 + mt * 16 + r]     = accH[nt * 4 + 1];
                D_hh[(n + 0) * 132 + mt * 16 + r + 8] = accH[nt * 4 + 2];
                D_hh[(n + 1) * 132 + mt * 16 + r + 8] = accH[nt * 4 + 3];
            }
        }
        __syncthreads();
        {
#pragma unroll
            for (int j = 0; j < 2; j++) {
                const int u = ug + j;
                float gi = D_s[(0 * 8 + u) * 132 + bl] + fmaf(mk, D_hh[(0 * 8 + u) * 132 + bl], bias1[j][0]);
                float gf = D_s[(1 * 8 + u) * 132 + bl] + fmaf(mk, D_hh[(1 * 8 + u) * 132 + bl], bias1[j][1]);
                float gg = D_s[(2 * 8 + u) * 132 + bl] + fmaf(mk, D_hh[(2 * 8 + u) * 132 + bl], bias1[j][2]);
                float go = D_s[(3 * 8 + u) * 132 + bl] + fmaf(mk, D_hh[(3 * 8 + u) * 132 + bl], bias1[j][3]);
                float c  = fmaf(sigmoidf_(gf), c1r[j] * mk, sigmoidf_(gi) * tanhf(gg));
                c1r[j]   = c;
                float h  = tf32r(sigmoidf_(go) * tanhf(c));
                g_h1[p ^ 1][b][u0 + u] = h;
                g_hidden[((size_t)t * BATCH + b) * HID + u0 + u] = h;
            }
        }
        // next step's top sync + grid_bar order everything else
    }

    grid_bar(++phase);

#pragma unroll
    for (int j = 0; j < 2; j++) {
        out_cT[(0 * BATCH + b) * HID + u0 + ug + j] = c0r[j];
        out_cT[(1 * BATCH + b) * HID + u0 + ug + j] = c1r[j];
    }
    for (int i = blockIdx.x * TPB + tid; i < BATCH * HID; i += NCTA * TPB) {
        out_hT[i]               = __ldcg(&(&g_h0[0][0][0])[i]);
        out_hT[BATCH * HID + i] = __ldcg(&(&g_h1[0][0][0])[i]);
    }
}

// ---------------- actor/critic heads -----------------------------------------
__global__ void __launch_bounds__(256)
head_kernel(const float* __restrict__ Wa, const float* __restrict__ ba,
            const float* __restrict__ Wc, const float* __restrict__ bc,
            float* __restrict__ out)
{
    __shared__ float Ws[NACT * HID];
    __shared__ float bs[NACT];
    for (int i = threadIdx.x; i < 18 * HID; i += blockDim.x) Ws[i] = Wa[i];
    for (int i = threadIdx.x; i < HID; i += blockDim.x) Ws[18 * HID + i] = Wc[i];
    if (threadIdx.x < 18) bs[threadIdx.x] = ba[threadIdx.x];
    if (threadIdx.x == 18) bs[18] = bc[0];
    __syncthreads();

    const int warp = threadIdx.x >> 5;
    const int lane = threadIdx.x & 31;
    const size_t m = (size_t)blockIdx.x * 8 + warp;

    const float* hrow = &g_hidden[m * HID];
    float hv[16];
#pragma unroll
    for (int j = 0; j < 16; j++) hv[j] = hrow[lane + j * 32];

#pragma unroll
    for (int a = 0; a < NACT; a++) {
        float s = 0.f;
#pragma unroll
        for (int j = 0; j < 16; j++) s = fmaf(hv[j], Ws[a * HID + lane + j * 32], s);
#pragma unroll
        for (int off = 16; off > 0; off >>= 1) s += __shfl_xor_sync(0xffffffffu, s, off);
        if (lane == a) out[m * NACT + a] = s + bs[a];
    }
}

// ---------------- launch ------------------------------------------------------
extern "C" void kernel_launch(void* const* d_in, const int* in_sizes, int n_in,
                              void* d_out, int out_size)
{
    (void)in_sizes; (void)n_in; (void)out_size;
    const float* x     = (const float*)d_in[0];
    const int*   done  = (const int*)  d_in[1];
    const float* h0    = (const float*)d_in[2];
    const float* c0    = (const float*)d_in[3];
    const float* W_ih0 = (const float*)d_in[4];
    const float* W_hh0 = (const float*)d_in[5];
    const float* b_ih0 = (const float*)d_in[6];
    const float* b_hh0 = (const float*)d_in[7];
    const float* W_ih1 = (const float*)d_in[8];
    const float* W_hh1 = (const float*)d_in[9];
    const float* b_ih1 = (const float*)d_in[10];
    const float* b_hh1 = (const float*)d_in[11];
    const float* W_a   = (const float*)d_in[12];
    const float* b_a   = (const float*)d_in[13];
    const float* W_c   = (const float*)d_in[14];
    const float* b_c   = (const float*)d_in[15];

    float* out    = (float*)d_out;
    float* out_hT = out + (size_t)T_STEPS * BATCH * NACT;
    float* out_cT = out_hT + 2 * BATCH * HID;

    cudaFuncSetAttribute(lstm_kernel, cudaFuncAttributeMaxDynamicSharedMemorySize, SM_TOTAL);
    cudaFuncSetAttribute(pre_mma_kernel, cudaFuncAttributeMaxDynamicSharedMemorySize, PM_TOTAL);

    init_kernel<<<64, 256>>>(h0);
    wt_kernel<<<132, 256>>>(W_hh0, W_ih1, W_hh1);

    dim3 gg(G4H / 128, (T_STEPS * BATCH) / 64);
    pre_mma_kernel<<<gg, 256, PM_TOTAL>>>(x, W_ih0, b_ih0, b_hh0);

    lstm_kernel<<<NCTA, TPB, SM_TOTAL>>>(done, c0, b_ih1, b_hh1, out_hT, out_cT);

    head_kernel<<<(T_STEPS * BATCH) / 8, 256>>>(W_a, b_a, W_c, b_c, out);
}